// round 11
// baseline (speedup 1.0000x reference)
#include <cuda_runtime.h>
#include <cuda_fp16.h>
#include <cstdint>

#define NSEG   256
#define PPTS   2000
#define NROWS  (NSEG * PPTS)      // 512000
#define GS     512                // stats grid
#define KTOT   64000
#define EPS_BN 1e-5f

// GEMM config: BM=128, BN=64, BK=64, single fp16 term, SPLITK=9
#define SPLITK 9
#define NSPL   9
#define TOTSLAB 1000              // KTOT/64
#define GEMM_CTAS (NSPL * 32)     // 288 (2 CTAs/SM, ~1 wave)
#define STG_BYTES 24576u          // A 16KB + B 8KB per stage
#define GEMM_SMEM (3 * 24576)     // 72 KB

#define BN2_J 8

// ---------------- device scratch (static, no allocations) ----------------
__device__ float g_p1[GS][32];
__device__ float g_p2[GS][16];
__device__ float g_p3[GS][2];
__device__ float g_ab1[32];
__device__ float g_ab2[16];
__device__ float g_ab3[2];
__device__ float g_z1[(size_t)NROWS * 16];             // 32 MB
__device__ float g_z2[(size_t)NROWS * 8];              // 16 MB
__device__ float g_z3[NROWS];                          // 2 MB
__device__ float g_att[NROWS];                         // 2 MB
__device__ __half g_ah[(size_t)NSEG * KTOT];           // 32.8 MB
__device__ __half g_bh[(size_t)1024 * KTOT];           // 131 MB
__device__ float g_part[(size_t)NSPL * 1024 * 256];    // 9.4 MB, [s][n][m]
__device__ float g_r1t[1024 * 256];                    // [o][b]
__device__ float g_r2[256 * 256];                      // [b][j]

// ---------------- helpers ----------------
__device__ __forceinline__ uint32_t s2u(const void* p) {
    uint32_t a;
    asm("{ .reg .u64 t; cvta.to.shared.u64 t, %1; cvt.u32.u64 %0, t; }" : "=r"(a) : "l"(p));
    return a;
}
__device__ __forceinline__ void cp16(uint32_t dst, const void* src) {
    asm volatile("cp.async.cg.shared.global [%0], [%1], 16;" :: "r"(dst), "l"(src));
}
__device__ __forceinline__ void ldm4(uint32_t* r, uint32_t a) {
    asm volatile("ldmatrix.sync.aligned.m8n8.x4.shared.b16 {%0,%1,%2,%3}, [%4];"
                 : "=r"(r[0]), "=r"(r[1]), "=r"(r[2]), "=r"(r[3]) : "r"(a));
}
__device__ __forceinline__ void mma16816(float* d, const uint32_t* a, uint32_t b0, uint32_t b1) {
    asm volatile("mma.sync.aligned.m16n8k16.row.col.f32.f16.f16.f32 "
                 "{%0,%1,%2,%3}, {%4,%5,%6,%7}, {%8,%9}, {%0,%1,%2,%3};"
                 : "+f"(d[0]), "+f"(d[1]), "+f"(d[2]), "+f"(d[3])
                 : "r"(a[0]), "r"(a[1]), "r"(a[2]), "r"(a[3]), "r"(b0), "r"(b1));
}
__device__ __forceinline__ uint32_t packh(float x, float y) {
    __half hx = __float2half_rn(x), hy = __float2half_rn(y);
    uint16_t ax = *(uint16_t*)&hx, ay = *(uint16_t*)&hy;
    return (uint32_t)ax | ((uint32_t)ay << 16);
}
__device__ __forceinline__ uint32_t sw128(uint32_t o) { return o ^ ((o >> 3) & 0x70u); }

// ---------------- convert fw1 -> fp16 (uint4 stores) ----------------
__global__ void k_convB(const float* __restrict__ w) {
    size_t n8 = (size_t)1024 * KTOT / 8;
    const float4* w4 = (const float4*)w;
    uint4* hi = (uint4*)g_bh;
    for (size_t i = (size_t)blockIdx.x * blockDim.x + threadIdx.x; i < n8;
         i += (size_t)gridDim.x * blockDim.x) {
        float4 a = w4[2 * i];
        float4 b = w4[2 * i + 1];
        hi[i] = make_uint4(packh(a.x, a.y), packh(a.z, a.w),
                           packh(b.x, b.y), packh(b.z, b.w));
    }
}

// ---------------- layer 1: z1 = x @ w1^T + b1, write z1, stats ----------------
__global__ void __launch_bounds__(256) k_stats1(const float* __restrict__ x,
                         const float* __restrict__ w1,
                         const float* __restrict__ b1) {
    __shared__ float sw[512];
    __shared__ float sb[16];
    __shared__ float red[8][32];
    int t = threadIdx.x;
    for (int i = t; i < 512; i += 256) sw[i] = w1[i];
    if (t < 16) sb[t] = b1[t];
    __syncthreads();

    float s[16], q[16];
#pragma unroll
    for (int j = 0; j < 16; j++) { s[j] = 0.f; q[j] = 0.f; }

    for (int r = blockIdx.x * 256 + t; r < NROWS; r += GS * 256) {
        const float4* xr = (const float4*)(x + (size_t)r * 32);
        float acc[16];
#pragma unroll
        for (int j = 0; j < 16; j++) acc[j] = sb[j];
#pragma unroll
        for (int c4 = 0; c4 < 8; c4++) {
            float4 v = xr[c4];
#pragma unroll
            for (int j = 0; j < 16; j++) {
                acc[j] += v.x * sw[j*32 + c4*4]
                        + v.y * sw[j*32 + c4*4 + 1]
                        + v.z * sw[j*32 + c4*4 + 2]
                        + v.w * sw[j*32 + c4*4 + 3];
            }
        }
        float4* zo = (float4*)(g_z1 + (size_t)r * 16);
#pragma unroll
        for (int c = 0; c < 4; c++)
            zo[c] = make_float4(acc[4*c], acc[4*c+1], acc[4*c+2], acc[4*c+3]);
#pragma unroll
        for (int j = 0; j < 16; j++) { s[j] += acc[j]; q[j] += acc[j] * acc[j]; }
    }
    int lane = t & 31, w = t >> 5;
#pragma unroll
    for (int j = 0; j < 16; j++) {
        float a = s[j], b = q[j];
        for (int o = 16; o > 0; o >>= 1) {
            a += __shfl_down_sync(0xffffffffu, a, o);
            b += __shfl_down_sync(0xffffffffu, b, o);
        }
        if (lane == 0) { red[w][j] = a; red[w][16 + j] = b; }
    }
    __syncthreads();
    if (t < 32) {
        float v = 0.f;
        for (int ww = 0; ww < 8; ww++) v += red[ww][t];
        g_p1[blockIdx.x][t] = v;
    }
}

__global__ void k_fin1(const float* __restrict__ g1, const float* __restrict__ be1) {
    __shared__ float sh[256];
    int t = threadIdx.x;
    int j = t & 31;
    float acc = 0.f;
    for (int b = t >> 5; b < GS; b += 8) acc += g_p1[b][j];
    sh[t] = acc; __syncthreads();
    for (int o = 128; o >= 32; o >>= 1) {
        if (t < o) sh[t] += sh[t + o];
        __syncthreads();
    }
    if (t < 16) {
        float m = sh[t] / (float)NROWS;
        float v = sh[16 + t] / (float)NROWS - m * m;
        float sc = g1[t] * rsqrtf(v + EPS_BN);
        g_ab1[t] = sc;
        g_ab1[16 + t] = be1[t] - m * sc;
    }
}

// ---------------- layer 2: h1 = relu(bn(z1)); z2 = h1 @ w2^T + b2 ----------------
__global__ void __launch_bounds__(256) k_stats2(const float* __restrict__ w2,
                                                const float* __restrict__ b2) {
    __shared__ float sw2[128], sb2[8], sc1[16], sh1[16];
    __shared__ float red[8][16];
    int t = threadIdx.x;
    for (int i = t; i < 128; i += 256) sw2[i] = w2[i];
    if (t < 16) { sc1[t] = g_ab1[t]; sh1[t] = g_ab1[16 + t]; }
    if (t < 8)  { sb2[t] = b2[t]; }
    __syncthreads();

    float s[8], q[8];
#pragma unroll
    for (int j = 0; j < 8; j++) { s[j] = 0.f; q[j] = 0.f; }

    for (int r = blockIdx.x * 256 + t; r < NROWS; r += GS * 256) {
        const float4* zr = (const float4*)(g_z1 + (size_t)r * 16);
        float acc[8];
#pragma unroll
        for (int j = 0; j < 8; j++) acc[j] = sb2[j];
#pragma unroll
        for (int c4 = 0; c4 < 4; c4++) {
            float4 v = zr[c4];
            float h0 = fmaxf(v.x * sc1[4*c4]   + sh1[4*c4],   0.f);
            float h1 = fmaxf(v.y * sc1[4*c4+1] + sh1[4*c4+1], 0.f);
            float h2 = fmaxf(v.z * sc1[4*c4+2] + sh1[4*c4+2], 0.f);
            float h3 = fmaxf(v.w * sc1[4*c4+3] + sh1[4*c4+3], 0.f);
#pragma unroll
            for (int j = 0; j < 8; j++) {
                acc[j] += h0 * sw2[j*16 + 4*c4]
                        + h1 * sw2[j*16 + 4*c4 + 1]
                        + h2 * sw2[j*16 + 4*c4 + 2]
                        + h3 * sw2[j*16 + 4*c4 + 3];
            }
        }
        float4* zo = (float4*)(g_z2 + (size_t)r * 8);
        zo[0] = make_float4(acc[0], acc[1], acc[2], acc[3]);
        zo[1] = make_float4(acc[4], acc[5], acc[6], acc[7]);
#pragma unroll
        for (int j = 0; j < 8; j++) { s[j] += acc[j]; q[j] += acc[j] * acc[j]; }
    }
    int lane = t & 31, w = t >> 5;
#pragma unroll
    for (int j = 0; j < 8; j++) {
        float a = s[j], b = q[j];
        for (int o = 16; o > 0; o >>= 1) {
            a += __shfl_down_sync(0xffffffffu, a, o);
            b += __shfl_down_sync(0xffffffffu, b, o);
        }
        if (lane == 0) { red[w][j] = a; red[w][8 + j] = b; }
    }
    __syncthreads();
    if (t < 16) {
        float v = 0.f;
        for (int ww = 0; ww < 8; ww++) v += red[ww][t];
        g_p2[blockIdx.x][t] = v;
    }
}

__global__ void k_fin2(const float* __restrict__ g2, const float* __restrict__ be2) {
    __shared__ float sh[256];
    int t = threadIdx.x;
    int j = t & 15;
    float acc = 0.f;
    for (int b = t >> 4; b < GS; b += 16) acc += g_p2[b][j];
    sh[t] = acc; __syncthreads();
    for (int o = 128; o >= 16; o >>= 1) {
        if (t < o) sh[t] += sh[t + o];
        __syncthreads();
    }
    if (t < 8) {
        float m = sh[t] / (float)NROWS;
        float v = sh[8 + t] / (float)NROWS - m * m;
        float sc = g2[t] * rsqrtf(v + EPS_BN);
        g_ab2[t] = sc;
        g_ab2[8 + t] = be2[t] - m * sc;
    }
}

// ---------------- layer 3 ----------------
__global__ void __launch_bounds__(256) k_stats3(const float* __restrict__ w3,
                                                const float* __restrict__ b3) {
    __shared__ float red[8][2];
    int t = threadIdx.x;
    float sc2[8], sh2[8], w3r[8];
#pragma unroll
    for (int c = 0; c < 8; c++) { sc2[c] = g_ab2[c]; sh2[c] = g_ab2[8 + c]; w3r[c] = w3[c]; }
    float b3v = b3[0];

    float s = 0.f, q = 0.f;
    for (int r = blockIdx.x * 256 + t; r < NROWS; r += GS * 256) {
        const float4* zr = (const float4*)(g_z2 + (size_t)r * 8);
        float4 a = zr[0], b = zr[1];
        float z2v[8] = {a.x, a.y, a.z, a.w, b.x, b.y, b.z, b.w};
        float z = b3v;
#pragma unroll
        for (int c = 0; c < 8; c++) z += fmaxf(z2v[c] * sc2[c] + sh2[c], 0.f) * w3r[c];
        g_z3[r] = z;
        s += z; q += z * z;
    }
    int lane = t & 31, w = t >> 5;
    for (int o = 16; o > 0; o >>= 1) {
        s += __shfl_down_sync(0xffffffffu, s, o);
        q += __shfl_down_sync(0xffffffffu, q, o);
    }
    if (lane == 0) { red[w][0] = s; red[w][1] = q; }
    __syncthreads();
    if (t < 2) {
        float v = 0.f;
        for (int ww = 0; ww < 8; ww++) v += red[ww][t];
        g_p3[blockIdx.x][t] = v;
    }
}

__global__ void k_fin3(const float* __restrict__ g3, const float* __restrict__ be3) {
    __shared__ float sh[256];
    int t = threadIdx.x;
    int j = t & 1;
    float acc = 0.f;
    for (int b = t >> 1; b < GS; b += 128) acc += g_p3[b][j];
    sh[t] = acc; __syncthreads();
    for (int o = 128; o >= 2; o >>= 1) {
        if (t < o) sh[t] += sh[t + o];
        __syncthreads();
    }
    if (t == 0) {
        float m = sh[0] / (float)NROWS;
        float v = sh[1] / (float)NROWS - m * m;
        float sc = g3[0] * rsqrtf(v + EPS_BN);
        g_ab3[0] = sc;
        g_ab3[1] = be3[0] - m * sc;
    }
}

// ---------------- softmax scores (att weights only) ----------------
__global__ void __launch_bounds__(256) k_soft() {
    __shared__ float ssc[PPTS];
    __shared__ float rbuf[256];
    int t = threadIdx.x, seg = blockIdx.x;
    float sc3 = g_ab3[0], sh3 = g_ab3[1];
    size_t base = (size_t)seg * PPTS;

    float mx = -1e30f;
    for (int p = t; p < PPTS; p += 256) {
        float s = fmaxf(g_z3[base + p] * sc3 + sh3, 0.f);
        ssc[p] = s;
        mx = fmaxf(mx, s);
    }
    rbuf[t] = mx; __syncthreads();
    for (int o = 128; o > 0; o >>= 1) {
        if (t < o) rbuf[t] = fmaxf(rbuf[t], rbuf[t + o]);
        __syncthreads();
    }
    mx = rbuf[0]; __syncthreads();

    float sm = 0.f;
    for (int p = t; p < PPTS; p += 256) {
        float e = expf(ssc[p] - mx);
        ssc[p] = e;
        sm += e;
    }
    rbuf[t] = sm; __syncthreads();
    for (int o = 128; o > 0; o >>= 1) {
        if (t < o) rbuf[t] += rbuf[t + o];
        __syncthreads();
    }
    float inv = 1.f / rbuf[0];
    __syncthreads();
    for (int p = t; p < PPTS; p += 256)
        g_att[base + p] = ssc[p] * inv;
}

// ---------------- pooling: ah = fp16(x * att), full-chip stream ----------------
__global__ void __launch_bounds__(256) k_pool(const float* __restrict__ x) {
    size_t n = (size_t)NROWS * 8;
    const float4* x4 = (const float4*)x;
    uint2* ah = (uint2*)g_ah;
    for (size_t i = (size_t)blockIdx.x * blockDim.x + threadIdx.x; i < n;
         i += (size_t)gridDim.x * blockDim.x) {
        float a = g_att[i >> 3];
        float4 v = x4[i];
        ah[i] = make_uint2(packh(v.x * a, v.y * a), packh(v.z * a, v.w * a));
    }
}

// ---------------- fc1 GEMM via mma.sync fp16, split-K ----------------
// grid: 288 CTAs = split(9) x mtile(2) x ntile(16). Per CTA: 128x64, K ~= 7111.
__global__ void __launch_bounds__(256, 2) k_gemm() {
    extern __shared__ char smraw[];
    const int t = threadIdx.x;
    const int lane = t & 31;
    const int w = t >> 5;
    const int wm = w >> 1;            // 0..3  (m-offset wm*32)
    const int wn = w & 1;             // 0..1  (n-offset wn*32)
    const int bx = blockIdx.x;
    const int nt = bx & 15;
    const int mt = (bx >> 4) & 1;
    const int ts = bx >> 5;           // 0..8 (split index)
    const int m0 = mt << 7;
    const int n0 = nt << 6;

    const int ks0 = (ts * TOTSLAB) / SPLITK;
    const int ks1 = ((ts + 1) * TOTSLAB) / SPLITK;
    const int iters = ks1 - ks0;

    const uint32_t sbase = s2u(smraw);

    const int arow = t >> 1;
    const int acb = (t & 1) * 4;
    const char* agp = (const char*)(g_ah + (size_t)(m0 + arow) * KTOT + ks0 * 64);
    uint32_t aoff[4];
#pragma unroll
    for (int c = 0; c < 4; c++)
        aoff[c] = sw128((uint32_t)arow * 128u + (uint32_t)(acb + c) * 16u);
    const int brow = t >> 2;
    const int bcb = (t & 3) * 2;
    const char* bgp = (const char*)(g_bh + (size_t)(n0 + brow) * KTOT + ks0 * 64);
    uint32_t boff[2];
#pragma unroll
    for (int c = 0; c < 2; c++)
        boff[c] = 16384u + sw128((uint32_t)brow * 128u + (uint32_t)(bcb + c) * 16u);

    const int rowa = wm * 32 + (lane & 15);
    const int rowb = wn * 32 + (lane & 15);
    const uint32_t xa = ((uint32_t)(rowa & 7)) << 4;
    const uint32_t xb = ((uint32_t)(rowb & 7)) << 4;
    uint32_t aob[2], bob[2];
#pragma unroll
    for (int mi = 0; mi < 2; mi++) aob[mi] = (uint32_t)(rowa + mi * 16) * 128u + ((lane >> 4) << 4);
#pragma unroll
    for (int ng = 0; ng < 2; ng++) bob[ng] = 16384u + (uint32_t)(rowb + ng * 16) * 128u + ((lane >> 4) << 4);

    float acc[2][4][4];
#pragma unroll
    for (int i = 0; i < 2; i++)
#pragma unroll
        for (int j = 0; j < 4; j++)
#pragma unroll
            for (int e = 0; e < 4; e++) acc[i][j][e] = 0.f;

#pragma unroll
    for (int p = 0; p < 2; p++) {
        uint32_t sb = sbase + p * STG_BYTES;
        const char* ag = agp + (size_t)p * 128;
        const char* bg = bgp + (size_t)p * 128;
#pragma unroll
        for (int c = 0; c < 4; c++) cp16(sb + aoff[c], ag + (acb + c) * 16);
#pragma unroll
        for (int c = 0; c < 2; c++) cp16(sb + boff[c], bg + (bcb + c) * 16);
        asm volatile("cp.async.commit_group;");
    }

    int stg = 0;
    for (int it = 0; it < iters; it++) {
        asm volatile("cp.async.wait_group 1;");
        __syncthreads();

        const uint32_t sa = sbase + (uint32_t)stg * STG_BYTES;
#pragma unroll
        for (int kk = 0; kk < 4; kk++) {
            uint32_t af[2][4], bf[2][4];
#pragma unroll
            for (int mi = 0; mi < 2; mi++)
                ldm4(af[mi], sa + ((aob[mi] + kk * 32) ^ xa));
#pragma unroll
            for (int ng = 0; ng < 2; ng++)
                ldm4(bf[ng], sa + ((bob[ng] + kk * 32) ^ xb));
#pragma unroll
            for (int mi = 0; mi < 2; mi++) {
                mma16816(acc[mi][0], af[mi], bf[0][0], bf[0][2]);
                mma16816(acc[mi][1], af[mi], bf[0][1], bf[0][3]);
                mma16816(acc[mi][2], af[mi], bf[1][0], bf[1][2]);
                mma16816(acc[mi][3], af[mi], bf[1][1], bf[1][3]);
            }
        }

        const int nx = it + 2;
        if (nx < iters) {
            uint32_t sb = sbase + (uint32_t)((stg + 2) % 3) * STG_BYTES;
            const char* ag = agp + (size_t)nx * 128;
            const char* bg = bgp + (size_t)nx * 128;
#pragma unroll
            for (int c = 0; c < 4; c++) cp16(sb + aoff[c], ag + (acb + c) * 16);
#pragma unroll
            for (int c = 0; c < 2; c++) cp16(sb + boff[c], bg + (bcb + c) * 16);
        }
        asm volatile("cp.async.commit_group;");
        stg = (stg + 1) % 3;
    }

#pragma unroll
    for (int mi = 0; mi < 2; mi++) {
        const int m = m0 + wm * 32 + mi * 16 + (lane >> 2);
#pragma unroll
        for (int nj = 0; nj < 4; nj++) {
            const int n = n0 + wn * 32 + nj * 8 + (lane & 3) * 2;
            float* d = g_part + ((size_t)ts * 1024 + n) * 256 + m;
            d[0]       = acc[mi][nj][0];
            d[256]     = acc[mi][nj][1];
            d[8]       = acc[mi][nj][2];
            d[256 + 8] = acc[mi][nj][3];
        }
    }
}

// ---------------- reduce split-K + BN over batch + relu (fc1) ----------------
__global__ void k_bn1(const float* __restrict__ fb1,
                      const float* __restrict__ fg1,
                      const float* __restrict__ fbe1) {
    __shared__ float rs[256], rq[256];
    int o = blockIdx.x, b = threadIdx.x;
    float pre = fb1[o];
#pragma unroll
    for (int s = 0; s < NSPL; s++)
        pre += g_part[((size_t)s * 1024 + o) * 256 + b];
    rs[b] = pre; rq[b] = pre * pre;
    __syncthreads();
    for (int o2 = 128; o2 > 0; o2 >>= 1) {
        if (b < o2) { rs[b] += rs[b + o2]; rq[b] += rq[b + o2]; }
        __syncthreads();
    }
    float m = rs[0] * (1.f / 256.f);
    float v = rq[0] * (1.f / 256.f) - m * m;
    float sc = fg1[o] * rsqrtf(v + EPS_BN);
    float sh = fbe1[o] - m * sc;
    g_r1t[(size_t)o * 256 + b] = fmaxf(pre * sc + sh, 0.f);
}

// ---------------- fc2 GEMM + BN over batch + relu (J-blocked, 8 j per CTA) ------
__global__ void __launch_bounds__(256) k_bn2(const float* __restrict__ fw2,
                      const float* __restrict__ fb2,
                      const float* __restrict__ fg2, const float* __restrict__ fbe2) {
    __shared__ float w[BN2_J][1024];   // 32 KB
    __shared__ float rs[256], rq[256];
    int j0 = blockIdx.x * BN2_J, b = threadIdx.x;
    for (int i = b; i < BN2_J * 1024; i += 256) {
        int jj = i >> 10, k = i & 1023;
        w[jj][k] = fw2[(size_t)(j0 + jj) * 1024 + k];
    }
    __syncthreads();
    float acc[BN2_J];
#pragma unroll
    for (int jj = 0; jj < BN2_J; jj++) acc[jj] = fb2[j0 + jj];
    for (int k = 0; k < 1024; k++) {
        float r = g_r1t[((size_t)k << 8) + b];
#pragma unroll
        for (int jj = 0; jj < BN2_J; jj++) acc[jj] += r * w[jj][k];
    }
#pragma unroll
    for (int jj = 0; jj < BN2_J; jj++) {
        rs[b] = acc[jj]; rq[b] = acc[jj] * acc[jj];
        __syncthreads();
        for (int o2 = 128; o2 > 0; o2 >>= 1) {
            if (b < o2) { rs[b] += rs[b + o2]; rq[b] += rq[b + o2]; }
            __syncthreads();
        }
        float m = rs[0] * (1.f / 256.f);
        float v = rq[0] * (1.f / 256.f) - m * m;
        float sc = fg2[j0 + jj] * rsqrtf(v + EPS_BN);
        float sh = fbe2[j0 + jj] - m * sc;
        g_r2[(size_t)b * 256 + j0 + jj] = fmaxf(acc[jj] * sc + sh, 0.f);
        __syncthreads();
    }
}

// ---------------- row-wise L2 normalize ----------------
__global__ void k_norm(float* __restrict__ out) {
    __shared__ float rs[256];
    int b = blockIdx.x, j = threadIdx.x;
    float v = g_r2[(size_t)b * 256 + j];
    rs[j] = v * v;
    __syncthreads();
    for (int o = 128; o > 0; o >>= 1) {
        if (j < o) rs[j] += rs[j + o];
        __syncthreads();
    }
    float nrm = fmaxf(sqrtf(rs[0]), 1e-12f);
    out[(size_t)b * 256 + j] = v / nrm;
}

// ---------------- launch ----------------
extern "C" void kernel_launch(void* const* d_in, const int* in_sizes, int n_in,
                              void* d_out, int out_size) {
    const float* x    = (const float*)d_in[0];
    const float* w1   = (const float*)d_in[2];
    const float* b1   = (const float*)d_in[3];
    const float* g1   = (const float*)d_in[4];
    const float* be1  = (const float*)d_in[5];
    const float* w2   = (const float*)d_in[6];
    const float* b2   = (const float*)d_in[7];
    const float* g2   = (const float*)d_in[8];
    const float* be2  = (const float*)d_in[9];
    const float* w3   = (const float*)d_in[10];
    const float* b3   = (const float*)d_in[11];
    const float* g3   = (const float*)d_in[12];
    const float* be3  = (const float*)d_in[13];
    const float* fw1  = (const float*)d_in[14];
    const float* fb1  = (const float*)d_in[15];
    const float* fg1  = (const float*)d_in[16];
    const float* fbe1 = (const float*)d_in[17];
    const float* fw2  = (const float*)d_in[18];
    const float* fb2  = (const float*)d_in[19];
    const float* fg2  = (const float*)d_in[20];
    const float* fbe2 = (const float*)d_in[21];
    float* out = (float*)d_out;

    cudaFuncSetAttribute(k_gemm, cudaFuncAttributeMaxDynamicSharedMemorySize, GEMM_SMEM);

    k_convB<<<1024, 256>>>(fw1);
    k_stats1<<<GS, 256>>>(x, w1, b1);
    k_fin1<<<1, 256>>>(g1, be1);
    k_stats2<<<GS, 256>>>(w2, b2);
    k_fin2<<<1, 256>>>(g2, be2);
    k_stats3<<<GS, 256>>>(w3, b3);
    k_fin3<<<1, 256>>>(g3, be3);
    k_soft<<<NSEG, 256>>>();
    k_pool<<<2048, 256>>>(x);
    k_gemm<<<GEMM_CTAS, 256, GEMM_SMEM>>>();
    k_bn1<<<1024, 256>>>(fb1, fg1, fbe1);
    k_bn2<<<256 / BN2_J, 256>>>(fw2, fb2, fg2, fbe2);
    k_norm<<<NSEG, 256>>>(out);
}

// round 12
// speedup vs baseline: 1.0754x; 1.0754x over previous
#include <cuda_runtime.h>
#include <cuda_fp16.h>
#include <cstdint>

#define NSEG   256
#define PPTS   2000
#define NROWS  (NSEG * PPTS)      // 512000
#define GS     512                // stats grid
#define KTOT   64000
#define EPS_BN 1e-5f

// GEMM config: BM=128, BN=64, BK=64, single fp16 term, SPLITK=9
#define SPLITK 9
#define NSPL   9
#define TOTSLAB 1000              // KTOT/64
#define GEMM_CTAS (NSPL * 32)     // 288 (2 CTAs/SM, ~1 wave)
#define STG_BYTES 24576u          // A 16KB + B 8KB per stage
#define GEMM_SMEM (3 * 24576)     // 72 KB

// ---------------- device scratch (static, no allocations) ----------------
__device__ float g_p1[GS][32];
__device__ float g_p2[GS][16];
__device__ float g_p3[GS][2];
__device__ float g_ab1[32];
__device__ float g_ab2[16];
__device__ float g_ab3[2];
__device__ float g_z1[(size_t)NROWS * 16];             // 32 MB
__device__ float g_z2[(size_t)NROWS * 8];              // 16 MB
__device__ float g_z3[NROWS];                          // 2 MB
__device__ __half g_ah[(size_t)NSEG * KTOT];           // 32.8 MB
__device__ __half g_bh[(size_t)1024 * KTOT];           // 131 MB
__device__ float g_part[(size_t)NSPL * 1024 * 256];    // 9.4 MB, [s][n][m]
__device__ float g_r1t[1024 * 256];                    // [o][b]
__device__ float g_r2[256 * 256];                      // [b][j]

// ---------------- helpers ----------------
__device__ __forceinline__ uint32_t s2u(const void* p) {
    uint32_t a;
    asm("{ .reg .u64 t; cvta.to.shared.u64 t, %1; cvt.u32.u64 %0, t; }" : "=r"(a) : "l"(p));
    return a;
}
__device__ __forceinline__ void cp16(uint32_t dst, const void* src) {
    asm volatile("cp.async.cg.shared.global [%0], [%1], 16;" :: "r"(dst), "l"(src));
}
__device__ __forceinline__ void ldm4(uint32_t* r, uint32_t a) {
    asm volatile("ldmatrix.sync.aligned.m8n8.x4.shared.b16 {%0,%1,%2,%3}, [%4];"
                 : "=r"(r[0]), "=r"(r[1]), "=r"(r[2]), "=r"(r[3]) : "r"(a));
}
__device__ __forceinline__ void mma16816(float* d, const uint32_t* a, uint32_t b0, uint32_t b1) {
    asm volatile("mma.sync.aligned.m16n8k16.row.col.f32.f16.f16.f32 "
                 "{%0,%1,%2,%3}, {%4,%5,%6,%7}, {%8,%9}, {%0,%1,%2,%3};"
                 : "+f"(d[0]), "+f"(d[1]), "+f"(d[2]), "+f"(d[3])
                 : "r"(a[0]), "r"(a[1]), "r"(a[2]), "r"(a[3]), "r"(b0), "r"(b1));
}
__device__ __forceinline__ uint32_t packh(float x, float y) {
    __half hx = __float2half_rn(x), hy = __float2half_rn(y);
    uint16_t ax = *(uint16_t*)&hx, ay = *(uint16_t*)&hy;
    return (uint32_t)ax | ((uint32_t)ay << 16);
}
__device__ __forceinline__ uint32_t sw128(uint32_t o) { return o ^ ((o >> 3) & 0x70u); }

// ---------------- convert fw1 -> fp16 (streaming hints, wide grid) ----------------
__global__ void k_convB(const float* __restrict__ w) {
    size_t n4 = (size_t)1024 * KTOT / 4;
    const float4* w4 = (const float4*)w;
    uint2* hi = (uint2*)g_bh;
    for (size_t i = (size_t)blockIdx.x * blockDim.x + threadIdx.x; i < n4;
         i += (size_t)gridDim.x * blockDim.x) {
        float4 v = __ldcs(&w4[i]);
        uint2 o = make_uint2(packh(v.x, v.y), packh(v.z, v.w));
        __stcs(&hi[i], o);
    }
}

// ---------------- layer 1: z1 = x @ w1^T + b1, write z1, stats ----------------
__global__ void __launch_bounds__(256) k_stats1(const float* __restrict__ x,
                         const float* __restrict__ w1,
                         const float* __restrict__ b1) {
    __shared__ float sw[512];
    __shared__ float sb[16];
    __shared__ float red[8][32];
    int t = threadIdx.x;
    for (int i = t; i < 512; i += 256) sw[i] = w1[i];
    if (t < 16) sb[t] = b1[t];
    __syncthreads();

    float s[16], q[16];
#pragma unroll
    for (int j = 0; j < 16; j++) { s[j] = 0.f; q[j] = 0.f; }

    for (int r = blockIdx.x * 256 + t; r < NROWS; r += GS * 256) {
        const float4* xr = (const float4*)(x + (size_t)r * 32);
        float acc[16];
#pragma unroll
        for (int j = 0; j < 16; j++) acc[j] = sb[j];
#pragma unroll
        for (int c4 = 0; c4 < 8; c4++) {
            float4 v = xr[c4];
#pragma unroll
            for (int j = 0; j < 16; j++) {
                acc[j] += v.x * sw[j*32 + c4*4]
                        + v.y * sw[j*32 + c4*4 + 1]
                        + v.z * sw[j*32 + c4*4 + 2]
                        + v.w * sw[j*32 + c4*4 + 3];
            }
        }
        float4* zo = (float4*)(g_z1 + (size_t)r * 16);
#pragma unroll
        for (int c = 0; c < 4; c++)
            zo[c] = make_float4(acc[4*c], acc[4*c+1], acc[4*c+2], acc[4*c+3]);
#pragma unroll
        for (int j = 0; j < 16; j++) { s[j] += acc[j]; q[j] += acc[j] * acc[j]; }
    }
    int lane = t & 31, w = t >> 5;
#pragma unroll
    for (int j = 0; j < 16; j++) {
        float a = s[j], b = q[j];
        for (int o = 16; o > 0; o >>= 1) {
            a += __shfl_down_sync(0xffffffffu, a, o);
            b += __shfl_down_sync(0xffffffffu, b, o);
        }
        if (lane == 0) { red[w][j] = a; red[w][16 + j] = b; }
    }
    __syncthreads();
    if (t < 32) {
        float v = 0.f;
        for (int ww = 0; ww < 8; ww++) v += red[ww][t];
        g_p1[blockIdx.x][t] = v;
    }
}

__global__ void k_fin1(const float* __restrict__ g1, const float* __restrict__ be1) {
    __shared__ float sh[256];
    int t = threadIdx.x;
    int j = t & 31;
    float acc = 0.f;
    for (int b = t >> 5; b < GS; b += 8) acc += g_p1[b][j];
    sh[t] = acc; __syncthreads();
    for (int o = 128; o >= 32; o >>= 1) {
        if (t < o) sh[t] += sh[t + o];
        __syncthreads();
    }
    if (t < 16) {
        float m = sh[t] / (float)NROWS;
        float v = sh[16 + t] / (float)NROWS - m * m;
        float sc = g1[t] * rsqrtf(v + EPS_BN);
        g_ab1[t] = sc;
        g_ab1[16 + t] = be1[t] - m * sc;
    }
}

// ---------------- layer 2: h1 = relu(bn(z1)); z2 = h1 @ w2^T + b2 ----------------
__global__ void __launch_bounds__(256) k_stats2(const float* __restrict__ w2,
                                                const float* __restrict__ b2) {
    __shared__ float sw2[128], sb2[8], sc1[16], sh1[16];
    __shared__ float red[8][16];
    int t = threadIdx.x;
    for (int i = t; i < 128; i += 256) sw2[i] = w2[i];
    if (t < 16) { sc1[t] = g_ab1[t]; sh1[t] = g_ab1[16 + t]; }
    if (t < 8)  { sb2[t] = b2[t]; }
    __syncthreads();

    float s[8], q[8];
#pragma unroll
    for (int j = 0; j < 8; j++) { s[j] = 0.f; q[j] = 0.f; }

    for (int r = blockIdx.x * 256 + t; r < NROWS; r += GS * 256) {
        const float4* zr = (const float4*)(g_z1 + (size_t)r * 16);
        float acc[8];
#pragma unroll
        for (int j = 0; j < 8; j++) acc[j] = sb2[j];
#pragma unroll
        for (int c4 = 0; c4 < 4; c4++) {
            float4 v = zr[c4];
            float h0 = fmaxf(v.x * sc1[4*c4]   + sh1[4*c4],   0.f);
            float h1 = fmaxf(v.y * sc1[4*c4+1] + sh1[4*c4+1], 0.f);
            float h2 = fmaxf(v.z * sc1[4*c4+2] + sh1[4*c4+2], 0.f);
            float h3 = fmaxf(v.w * sc1[4*c4+3] + sh1[4*c4+3], 0.f);
#pragma unroll
            for (int j = 0; j < 8; j++) {
                acc[j] += h0 * sw2[j*16 + 4*c4]
                        + h1 * sw2[j*16 + 4*c4 + 1]
                        + h2 * sw2[j*16 + 4*c4 + 2]
                        + h3 * sw2[j*16 + 4*c4 + 3];
            }
        }
        float4* zo = (float4*)(g_z2 + (size_t)r * 8);
        zo[0] = make_float4(acc[0], acc[1], acc[2], acc[3]);
        zo[1] = make_float4(acc[4], acc[5], acc[6], acc[7]);
#pragma unroll
        for (int j = 0; j < 8; j++) { s[j] += acc[j]; q[j] += acc[j] * acc[j]; }
    }
    int lane = t & 31, w = t >> 5;
#pragma unroll
    for (int j = 0; j < 8; j++) {
        float a = s[j], b = q[j];
        for (int o = 16; o > 0; o >>= 1) {
            a += __shfl_down_sync(0xffffffffu, a, o);
            b += __shfl_down_sync(0xffffffffu, b, o);
        }
        if (lane == 0) { red[w][j] = a; red[w][8 + j] = b; }
    }
    __syncthreads();
    if (t < 16) {
        float v = 0.f;
        for (int ww = 0; ww < 8; ww++) v += red[ww][t];
        g_p2[blockIdx.x][t] = v;
    }
}

__global__ void k_fin2(const float* __restrict__ g2, const float* __restrict__ be2) {
    __shared__ float sh[256];
    int t = threadIdx.x;
    int j = t & 15;
    float acc = 0.f;
    for (int b = t >> 4; b < GS; b += 16) acc += g_p2[b][j];
    sh[t] = acc; __syncthreads();
    for (int o = 128; o >= 16; o >>= 1) {
        if (t < o) sh[t] += sh[t + o];
        __syncthreads();
    }
    if (t < 8) {
        float m = sh[t] / (float)NROWS;
        float v = sh[8 + t] / (float)NROWS - m * m;
        float sc = g2[t] * rsqrtf(v + EPS_BN);
        g_ab2[t] = sc;
        g_ab2[8 + t] = be2[t] - m * sc;
    }
}

// ---------------- layer 3 ----------------
__global__ void __launch_bounds__(256) k_stats3(const float* __restrict__ w3,
                                                const float* __restrict__ b3) {
    __shared__ float red[8][2];
    int t = threadIdx.x;
    float sc2[8], sh2[8], w3r[8];
#pragma unroll
    for (int c = 0; c < 8; c++) { sc2[c] = g_ab2[c]; sh2[c] = g_ab2[8 + c]; w3r[c] = w3[c]; }
    float b3v = b3[0];

    float s = 0.f, q = 0.f;
    for (int r = blockIdx.x * 256 + t; r < NROWS; r += GS * 256) {
        const float4* zr = (const float4*)(g_z2 + (size_t)r * 8);
        float4 a = zr[0], b = zr[1];
        float z2v[8] = {a.x, a.y, a.z, a.w, b.x, b.y, b.z, b.w};
        float z = b3v;
#pragma unroll
        for (int c = 0; c < 8; c++) z += fmaxf(z2v[c] * sc2[c] + sh2[c], 0.f) * w3r[c];
        g_z3[r] = z;
        s += z; q += z * z;
    }
    int lane = t & 31, w = t >> 5;
    for (int o = 16; o > 0; o >>= 1) {
        s += __shfl_down_sync(0xffffffffu, s, o);
        q += __shfl_down_sync(0xffffffffu, q, o);
    }
    if (lane == 0) { red[w][0] = s; red[w][1] = q; }
    __syncthreads();
    if (t < 2) {
        float v = 0.f;
        for (int ww = 0; ww < 8; ww++) v += red[ww][t];
        g_p3[blockIdx.x][t] = v;
    }
}

__global__ void k_fin3(const float* __restrict__ g3, const float* __restrict__ be3) {
    __shared__ float sh[256];
    int t = threadIdx.x;
    int j = t & 1;
    float acc = 0.f;
    for (int b = t >> 1; b < GS; b += 128) acc += g_p3[b][j];
    sh[t] = acc; __syncthreads();
    for (int o = 128; o >= 2; o >>= 1) {
        if (t < o) sh[t] += sh[t + o];
        __syncthreads();
    }
    if (t == 0) {
        float m = sh[0] / (float)NROWS;
        float v = sh[1] / (float)NROWS - m * m;
        float sc = g3[0] * rsqrtf(v + EPS_BN);
        g_ab3[0] = sc;
        g_ab3[1] = be3[0] - m * sc;
    }
}

// ---------------- softmax + pooling; writes A fp16 ----------------
__global__ void __launch_bounds__(256) k_soft(const float* __restrict__ x) {
    __shared__ float ssc[PPTS];
    __shared__ float rbuf[256];
    int t = threadIdx.x, seg = blockIdx.x;
    float sc3 = g_ab3[0], sh3 = g_ab3[1];
    size_t base = (size_t)seg * PPTS;

    float mx = -1e30f;
    for (int p = t; p < PPTS; p += 256) {
        float s = fmaxf(g_z3[base + p] * sc3 + sh3, 0.f);
        ssc[p] = s;
        mx = fmaxf(mx, s);
    }
    rbuf[t] = mx; __syncthreads();
    for (int o = 128; o > 0; o >>= 1) {
        if (t < o) rbuf[t] = fmaxf(rbuf[t], rbuf[t + o]);
        __syncthreads();
    }
    mx = rbuf[0]; __syncthreads();

    float sm = 0.f;
    for (int p = t; p < PPTS; p += 256) {
        float e = expf(ssc[p] - mx);
        ssc[p] = e;
        sm += e;
    }
    rbuf[t] = sm; __syncthreads();
    for (int o = 128; o > 0; o >>= 1) {
        if (t < o) rbuf[t] += rbuf[t + o];
        __syncthreads();
    }
    float inv = 1.f / rbuf[0];
    __syncthreads();
    for (int p = t; p < PPTS; p += 256) ssc[p] *= inv;
    __syncthreads();

    const float4* x4 = (const float4*)x;
    uint2* ah = (uint2*)g_ah;
    for (int i = t; i < PPTS * 8; i += 256) {
        float a = ssc[i >> 3];
        float4 v = x4[base * 8 + i];
        ah[(size_t)seg * (KTOT / 4) + i] =
            make_uint2(packh(v.x * a, v.y * a), packh(v.z * a, v.w * a));
    }
}

// ---------------- fc1 GEMM via mma.sync fp16, split-K ----------------
// grid: 288 CTAs = split(9) x mtile(2) x ntile(16). Per CTA: 128x64, K ~= 7111.
__global__ void __launch_bounds__(256, 2) k_gemm() {
    extern __shared__ char smraw[];
    const int t = threadIdx.x;
    const int lane = t & 31;
    const int w = t >> 5;
    const int wm = w >> 1;            // 0..3  (m-offset wm*32)
    const int wn = w & 1;             // 0..1  (n-offset wn*32)
    const int bx = blockIdx.x;
    const int nt = bx & 15;
    const int mt = (bx >> 4) & 1;
    const int ts = bx >> 5;           // 0..8 (split index)
    const int m0 = mt << 7;
    const int n0 = nt << 6;

    const int ks0 = (ts * TOTSLAB) / SPLITK;
    const int ks1 = ((ts + 1) * TOTSLAB) / SPLITK;
    const int iters = ks1 - ks0;

    const uint32_t sbase = s2u(smraw);

    const int arow = t >> 1;
    const int acb = (t & 1) * 4;
    const char* agp = (const char*)(g_ah + (size_t)(m0 + arow) * KTOT + ks0 * 64);
    uint32_t aoff[4];
#pragma unroll
    for (int c = 0; c < 4; c++)
        aoff[c] = sw128((uint32_t)arow * 128u + (uint32_t)(acb + c) * 16u);
    const int brow = t >> 2;
    const int bcb = (t & 3) * 2;
    const char* bgp = (const char*)(g_bh + (size_t)(n0 + brow) * KTOT + ks0 * 64);
    uint32_t boff[2];
#pragma unroll
    for (int c = 0; c < 2; c++)
        boff[c] = 16384u + sw128((uint32_t)brow * 128u + (uint32_t)(bcb + c) * 16u);

    const int rowa = wm * 32 + (lane & 15);
    const int rowb = wn * 32 + (lane & 15);
    const uint32_t xa = ((uint32_t)(rowa & 7)) << 4;
    const uint32_t xb = ((uint32_t)(rowb & 7)) << 4;
    uint32_t aob[2], bob[2];
#pragma unroll
    for (int mi = 0; mi < 2; mi++) aob[mi] = (uint32_t)(rowa + mi * 16) * 128u + ((lane >> 4) << 4);
#pragma unroll
    for (int ng = 0; ng < 2; ng++) bob[ng] = 16384u + (uint32_t)(rowb + ng * 16) * 128u + ((lane >> 4) << 4);

    float acc[2][4][4];
#pragma unroll
    for (int i = 0; i < 2; i++)
#pragma unroll
        for (int j = 0; j < 4; j++)
#pragma unroll
            for (int e = 0; e < 4; e++) acc[i][j][e] = 0.f;

#pragma unroll
    for (int p = 0; p < 2; p++) {
        uint32_t sb = sbase + p * STG_BYTES;
        const char* ag = agp + (size_t)p * 128;
        const char* bg = bgp + (size_t)p * 128;
#pragma unroll
        for (int c = 0; c < 4; c++) cp16(sb + aoff[c], ag + (acb + c) * 16);
#pragma unroll
        for (int c = 0; c < 2; c++) cp16(sb + boff[c], bg + (bcb + c) * 16);
        asm volatile("cp.async.commit_group;");
    }

    int stg = 0;
    for (int it = 0; it < iters; it++) {
        asm volatile("cp.async.wait_group 1;");
        __syncthreads();

        const uint32_t sa = sbase + (uint32_t)stg * STG_BYTES;
#pragma unroll
        for (int kk = 0; kk < 4; kk++) {
            uint32_t af[2][4], bf[2][4];
#pragma unroll
            for (int mi = 0; mi < 2; mi++)
                ldm4(af[mi], sa + ((aob[mi] + kk * 32) ^ xa));
#pragma unroll
            for (int ng = 0; ng < 2; ng++)
                ldm4(bf[ng], sa + ((bob[ng] + kk * 32) ^ xb));
#pragma unroll
            for (int mi = 0; mi < 2; mi++) {
                mma16816(acc[mi][0], af[mi], bf[0][0], bf[0][2]);
                mma16816(acc[mi][1], af[mi], bf[0][1], bf[0][3]);
                mma16816(acc[mi][2], af[mi], bf[1][0], bf[1][2]);
                mma16816(acc[mi][3], af[mi], bf[1][1], bf[1][3]);
            }
        }

        const int nx = it + 2;
        if (nx < iters) {
            uint32_t sb = sbase + (uint32_t)((stg + 2) % 3) * STG_BYTES;
            const char* ag = agp + (size_t)nx * 128;
            const char* bg = bgp + (size_t)nx * 128;
#pragma unroll
            for (int c = 0; c < 4; c++) cp16(sb + aoff[c], ag + (acb + c) * 16);
#pragma unroll
            for (int c = 0; c < 2; c++) cp16(sb + boff[c], bg + (bcb + c) * 16);
        }
        asm volatile("cp.async.commit_group;");
        stg = (stg + 1) % 3;
    }

#pragma unroll
    for (int mi = 0; mi < 2; mi++) {
        const int m = m0 + wm * 32 + mi * 16 + (lane >> 2);
#pragma unroll
        for (int nj = 0; nj < 4; nj++) {
            const int n = n0 + wn * 32 + nj * 8 + (lane & 3) * 2;
            float* d = g_part + ((size_t)ts * 1024 + n) * 256 + m;
            d[0]       = acc[mi][nj][0];
            d[256]     = acc[mi][nj][1];
            d[8]       = acc[mi][nj][2];
            d[256 + 8] = acc[mi][nj][3];
        }
    }
}

// ---------------- reduce split-K + BN over batch + relu (fc1) ----------------
__global__ void k_bn1(const float* __restrict__ fb1,
                      const float* __restrict__ fg1,
                      const float* __restrict__ fbe1) {
    __shared__ float rs[256], rq[256];
    int o = blockIdx.x, b = threadIdx.x;
    float pre = fb1[o];
#pragma unroll
    for (int s = 0; s < NSPL; s++)
        pre += g_part[((size_t)s * 1024 + o) * 256 + b];
    rs[b] = pre; rq[b] = pre * pre;
    __syncthreads();
    for (int o2 = 128; o2 > 0; o2 >>= 1) {
        if (b < o2) { rs[b] += rs[b + o2]; rq[b] += rq[b + o2]; }
        __syncthreads();
    }
    float m = rs[0] * (1.f / 256.f);
    float v = rq[0] * (1.f / 256.f) - m * m;
    float sc = fg1[o] * rsqrtf(v + EPS_BN);
    float sh = fbe1[o] - m * sc;
    g_r1t[(size_t)o * 256 + b] = fmaxf(pre * sc + sh, 0.f);
}

// ---------------- fc2 GEMM + BN over batch + relu ----------------
__global__ void k_bn2(const float* __restrict__ fw2, const float* __restrict__ fb2,
                      const float* __restrict__ fg2, const float* __restrict__ fbe2) {
    __shared__ float w[1024];
    __shared__ float rs[256], rq[256];
    int j = blockIdx.x, b = threadIdx.x;
    for (int i = b; i < 1024; i += 256) w[i] = fw2[(size_t)j * 1024 + i];
    __syncthreads();
    float pre = fb2[j];
#pragma unroll 8
    for (int k = 0; k < 1024; k++)
        pre += g_r1t[((size_t)k << 8) + b] * w[k];
    rs[b] = pre; rq[b] = pre * pre;
    __syncthreads();
    for (int o2 = 128; o2 > 0; o2 >>= 1) {
        if (b < o2) { rs[b] += rs[b + o2]; rq[b] += rq[b + o2]; }
        __syncthreads();
    }
    float m = rs[0] * (1.f / 256.f);
    float v = rq[0] * (1.f / 256.f) - m * m;
    float sc = fg2[j] * rsqrtf(v + EPS_BN);
    float sh = fbe2[j] - m * sc;
    g_r2[(size_t)b * 256 + j] = fmaxf(pre * sc + sh, 0.f);
}

// ---------------- row-wise L2 normalize ----------------
__global__ void k_norm(float* __restrict__ out) {
    __shared__ float rs[256];
    int b = blockIdx.x, j = threadIdx.x;
    float v = g_r2[(size_t)b * 256 + j];
    rs[j] = v * v;
    __syncthreads();
    for (int o = 128; o > 0; o >>= 1) {
        if (j < o) rs[j] += rs[j + o];
        __syncthreads();
    }
    float nrm = fmaxf(sqrtf(rs[0]), 1e-12f);
    out[(size_t)b * 256 + j] = v / nrm;
}

// ---------------- launch (convB moved to index 3 so ncu captures it) ----------------
extern "C" void kernel_launch(void* const* d_in, const int* in_sizes, int n_in,
                              void* d_out, int out_size) {
    const float* x    = (const float*)d_in[0];
    const float* w1   = (const float*)d_in[2];
    const float* b1   = (const float*)d_in[3];
    const float* g1   = (const float*)d_in[4];
    const float* be1  = (const float*)d_in[5];
    const float* w2   = (const float*)d_in[6];
    const float* b2   = (const float*)d_in[7];
    const float* g2   = (const float*)d_in[8];
    const float* be2  = (const float*)d_in[9];
    const float* w3   = (const float*)d_in[10];
    const float* b3   = (const float*)d_in[11];
    const float* g3   = (const float*)d_in[12];
    const float* be3  = (const float*)d_in[13];
    const float* fw1  = (const float*)d_in[14];
    const float* fb1  = (const float*)d_in[15];
    const float* fg1  = (const float*)d_in[16];
    const float* fbe1 = (const float*)d_in[17];
    const float* fw2  = (const float*)d_in[18];
    const float* fb2  = (const float*)d_in[19];
    const float* fg2  = (const float*)d_in[20];
    const float* fbe2 = (const float*)d_in[21];
    float* out = (float*)d_out;

    cudaFuncSetAttribute(k_gemm, cudaFuncAttributeMaxDynamicSharedMemorySize, GEMM_SMEM);

    k_stats1<<<GS, 256>>>(x, w1, b1);
    k_fin1<<<1, 256>>>(g1, be1);
    k_stats2<<<GS, 256>>>(w2, b2);
    k_convB<<<2048, 256>>>(fw1);          // index 3 -> ncu capture target
    k_fin2<<<1, 256>>>(g2, be2);
    k_stats3<<<GS, 256>>>(w3, b3);
    k_fin3<<<1, 256>>>(g3, be3);
    k_soft<<<NSEG, 256>>>(x);
    k_gemm<<<GEMM_CTAS, 256, GEMM_SMEM>>>();
    k_bn1<<<1024, 256>>>(fb1, fg1, fbe1);
    k_bn2<<<256, 256>>>(fw2, fb2, fg2, fbe2);
    k_norm<<<NSEG, 256>>>(out);
}

// round 13
// speedup vs baseline: 1.1014x; 1.0242x over previous
#include <cuda_runtime.h>
#include <cuda_fp16.h>
#include <cstdint>

#define NSEG   256
#define PPTS   2000
#define NROWS  (NSEG * PPTS)      // 512000
#define GS     512                // stats grid
#define KTOT   64000
#define EPS_BN 1e-5f

// GEMM config: BM=256, BN=128, BK=64, single fp16 term, SPLITK=18, 512 threads
#define SPLITK 18
#define NSPL   18
#define TOTSLAB 1000              // KTOT/64
#define GEMM_CTAS (NSPL * 8)      // 144 CTAs = one wave @ 1 CTA/SM
#define STG_BYTES 49152u          // A 32KB + B 16KB per stage
#define GEMM_SMEM (3 * 49152)     // 144 KB

// ---------------- device scratch (static, no allocations) ----------------
__device__ float g_p1[GS][32];
__device__ float g_p2[GS][16];
__device__ float g_p3[GS][2];
__device__ float g_ab1[32];
__device__ float g_ab2[16];
__device__ float g_ab3[2];
__device__ float g_z1[(size_t)NROWS * 16];             // 32 MB
__device__ float g_z2[(size_t)NROWS * 8];              // 16 MB
__device__ float g_z3[NROWS];                          // 2 MB
__device__ __half g_ah[(size_t)NSEG * KTOT];           // 32.8 MB
__device__ __half g_bh[(size_t)1024 * KTOT];           // 131 MB
__device__ float g_part[(size_t)NSPL * 1024 * 256];    // 18.9 MB, [s][n][m]
__device__ float g_r1t[1024 * 256];                    // [o][b]
__device__ float g_r2[256 * 256];                      // [b][j]

// ---------------- helpers ----------------
__device__ __forceinline__ uint32_t s2u(const void* p) {
    uint32_t a;
    asm("{ .reg .u64 t; cvta.to.shared.u64 t, %1; cvt.u32.u64 %0, t; }" : "=r"(a) : "l"(p));
    return a;
}
__device__ __forceinline__ void cp16(uint32_t dst, const void* src) {
    asm volatile("cp.async.cg.shared.global [%0], [%1], 16;" :: "r"(dst), "l"(src));
}
__device__ __forceinline__ void ldm4(uint32_t* r, uint32_t a) {
    asm volatile("ldmatrix.sync.aligned.m8n8.x4.shared.b16 {%0,%1,%2,%3}, [%4];"
                 : "=r"(r[0]), "=r"(r[1]), "=r"(r[2]), "=r"(r[3]) : "r"(a));
}
__device__ __forceinline__ void mma16816(float* d, const uint32_t* a, uint32_t b0, uint32_t b1) {
    asm volatile("mma.sync.aligned.m16n8k16.row.col.f32.f16.f16.f32 "
                 "{%0,%1,%2,%3}, {%4,%5,%6,%7}, {%8,%9}, {%0,%1,%2,%3};"
                 : "+f"(d[0]), "+f"(d[1]), "+f"(d[2]), "+f"(d[3])
                 : "r"(a[0]), "r"(a[1]), "r"(a[2]), "r"(a[3]), "r"(b0), "r"(b1));
}
__device__ __forceinline__ uint32_t packh(float x, float y) {
    __half hx = __float2half_rn(x), hy = __float2half_rn(y);
    uint16_t ax = *(uint16_t*)&hx, ay = *(uint16_t*)&hy;
    return (uint32_t)ax | ((uint32_t)ay << 16);
}
__device__ __forceinline__ uint32_t sw128(uint32_t o) { return o ^ ((o >> 3) & 0x70u); }

// ---------------- convert fw1 -> fp16 (streaming hints) ----------------
__global__ void k_convB(const float* __restrict__ w) {
    size_t n4 = (size_t)1024 * KTOT / 4;
    const float4* w4 = (const float4*)w;
    uint2* hi = (uint2*)g_bh;
    for (size_t i = (size_t)blockIdx.x * blockDim.x + threadIdx.x; i < n4;
         i += (size_t)gridDim.x * blockDim.x) {
        float4 v = __ldcs(&w4[i]);
        uint2 o = make_uint2(packh(v.x, v.y), packh(v.z, v.w));
        __stcs(&hi[i], o);
    }
}

// ---------------- layer 1: z1 = x @ w1^T + b1, write z1, stats ----------------
__global__ void __launch_bounds__(256) k_stats1(const float* __restrict__ x,
                         const float* __restrict__ w1,
                         const float* __restrict__ b1) {
    __shared__ float sw[512];
    __shared__ float sb[16];
    __shared__ float red[8][32];
    int t = threadIdx.x;
    for (int i = t; i < 512; i += 256) sw[i] = w1[i];
    if (t < 16) sb[t] = b1[t];
    __syncthreads();

    float s[16], q[16];
#pragma unroll
    for (int j = 0; j < 16; j++) { s[j] = 0.f; q[j] = 0.f; }

    for (int r = blockIdx.x * 256 + t; r < NROWS; r += GS * 256) {
        const float4* xr = (const float4*)(x + (size_t)r * 32);
        float acc[16];
#pragma unroll
        for (int j = 0; j < 16; j++) acc[j] = sb[j];
#pragma unroll
        for (int c4 = 0; c4 < 8; c4++) {
            float4 v = xr[c4];
#pragma unroll
            for (int j = 0; j < 16; j++) {
                acc[j] += v.x * sw[j*32 + c4*4]
                        + v.y * sw[j*32 + c4*4 + 1]
                        + v.z * sw[j*32 + c4*4 + 2]
                        + v.w * sw[j*32 + c4*4 + 3];
            }
        }
        float4* zo = (float4*)(g_z1 + (size_t)r * 16);
#pragma unroll
        for (int c = 0; c < 4; c++)
            zo[c] = make_float4(acc[4*c], acc[4*c+1], acc[4*c+2], acc[4*c+3]);
#pragma unroll
        for (int j = 0; j < 16; j++) { s[j] += acc[j]; q[j] += acc[j] * acc[j]; }
    }
    int lane = t & 31, w = t >> 5;
#pragma unroll
    for (int j = 0; j < 16; j++) {
        float a = s[j], b = q[j];
        for (int o = 16; o > 0; o >>= 1) {
            a += __shfl_down_sync(0xffffffffu, a, o);
            b += __shfl_down_sync(0xffffffffu, b, o);
        }
        if (lane == 0) { red[w][j] = a; red[w][16 + j] = b; }
    }
    __syncthreads();
    if (t < 32) {
        float v = 0.f;
        for (int ww = 0; ww < 8; ww++) v += red[ww][t];
        g_p1[blockIdx.x][t] = v;
    }
}

__global__ void k_fin1(const float* __restrict__ g1, const float* __restrict__ be1) {
    __shared__ float sh[256];
    int t = threadIdx.x;
    int j = t & 31;
    float acc = 0.f;
    for (int b = t >> 5; b < GS; b += 8) acc += g_p1[b][j];
    sh[t] = acc; __syncthreads();
    for (int o = 128; o >= 32; o >>= 1) {
        if (t < o) sh[t] += sh[t + o];
        __syncthreads();
    }
    if (t < 16) {
        float m = sh[t] / (float)NROWS;
        float v = sh[16 + t] / (float)NROWS - m * m;
        float sc = g1[t] * rsqrtf(v + EPS_BN);
        g_ab1[t] = sc;
        g_ab1[16 + t] = be1[t] - m * sc;
    }
}

// ---------------- layer 2: h1 = relu(bn(z1)); z2 = h1 @ w2^T + b2 ----------------
__global__ void __launch_bounds__(256) k_stats2(const float* __restrict__ w2,
                                                const float* __restrict__ b2) {
    __shared__ float sw2[128], sb2[8], sc1[16], sh1[16];
    __shared__ float red[8][16];
    int t = threadIdx.x;
    for (int i = t; i < 128; i += 256) sw2[i] = w2[i];
    if (t < 16) { sc1[t] = g_ab1[t]; sh1[t] = g_ab1[16 + t]; }
    if (t < 8)  { sb2[t] = b2[t]; }
    __syncthreads();

    float s[8], q[8];
#pragma unroll
    for (int j = 0; j < 8; j++) { s[j] = 0.f; q[j] = 0.f; }

    for (int r = blockIdx.x * 256 + t; r < NROWS; r += GS * 256) {
        const float4* zr = (const float4*)(g_z1 + (size_t)r * 16);
        float acc[8];
#pragma unroll
        for (int j = 0; j < 8; j++) acc[j] = sb2[j];
#pragma unroll
        for (int c4 = 0; c4 < 4; c4++) {
            float4 v = zr[c4];
            float h0 = fmaxf(v.x * sc1[4*c4]   + sh1[4*c4],   0.f);
            float h1 = fmaxf(v.y * sc1[4*c4+1] + sh1[4*c4+1], 0.f);
            float h2 = fmaxf(v.z * sc1[4*c4+2] + sh1[4*c4+2], 0.f);
            float h3 = fmaxf(v.w * sc1[4*c4+3] + sh1[4*c4+3], 0.f);
#pragma unroll
            for (int j = 0; j < 8; j++) {
                acc[j] += h0 * sw2[j*16 + 4*c4]
                        + h1 * sw2[j*16 + 4*c4 + 1]
                        + h2 * sw2[j*16 + 4*c4 + 2]
                        + h3 * sw2[j*16 + 4*c4 + 3];
            }
        }
        float4* zo = (float4*)(g_z2 + (size_t)r * 8);
        zo[0] = make_float4(acc[0], acc[1], acc[2], acc[3]);
        zo[1] = make_float4(acc[4], acc[5], acc[6], acc[7]);
#pragma unroll
        for (int j = 0; j < 8; j++) { s[j] += acc[j]; q[j] += acc[j] * acc[j]; }
    }
    int lane = t & 31, w = t >> 5;
#pragma unroll
    for (int j = 0; j < 8; j++) {
        float a = s[j], b = q[j];
        for (int o = 16; o > 0; o >>= 1) {
            a += __shfl_down_sync(0xffffffffu, a, o);
            b += __shfl_down_sync(0xffffffffu, b, o);
        }
        if (lane == 0) { red[w][j] = a; red[w][8 + j] = b; }
    }
    __syncthreads();
    if (t < 16) {
        float v = 0.f;
        for (int ww = 0; ww < 8; ww++) v += red[ww][t];
        g_p2[blockIdx.x][t] = v;
    }
}

__global__ void k_fin2(const float* __restrict__ g2, const float* __restrict__ be2) {
    __shared__ float sh[256];
    int t = threadIdx.x;
    int j = t & 15;
    float acc = 0.f;
    for (int b = t >> 4; b < GS; b += 16) acc += g_p2[b][j];
    sh[t] = acc; __syncthreads();
    for (int o = 128; o >= 16; o >>= 1) {
        if (t < o) sh[t] += sh[t + o];
        __syncthreads();
    }
    if (t < 8) {
        float m = sh[t] / (float)NROWS;
        float v = sh[8 + t] / (float)NROWS - m * m;
        float sc = g2[t] * rsqrtf(v + EPS_BN);
        g_ab2[t] = sc;
        g_ab2[8 + t] = be2[t] - m * sc;
    }
}

// ---------------- layer 3 ----------------
__global__ void __launch_bounds__(256) k_stats3(const float* __restrict__ w3,
                                                const float* __restrict__ b3) {
    __shared__ float red[8][2];
    int t = threadIdx.x;
    float sc2[8], sh2[8], w3r[8];
#pragma unroll
    for (int c = 0; c < 8; c++) { sc2[c] = g_ab2[c]; sh2[c] = g_ab2[8 + c]; w3r[c] = w3[c]; }
    float b3v = b3[0];

    float s = 0.f, q = 0.f;
    for (int r = blockIdx.x * 256 + t; r < NROWS; r += GS * 256) {
        const float4* zr = (const float4*)(g_z2 + (size_t)r * 8);
        float4 a = zr[0], b = zr[1];
        float z2v[8] = {a.x, a.y, a.z, a.w, b.x, b.y, b.z, b.w};
        float z = b3v;
#pragma unroll
        for (int c = 0; c < 8; c++) z += fmaxf(z2v[c] * sc2[c] + sh2[c], 0.f) * w3r[c];
        g_z3[r] = z;
        s += z; q += z * z;
    }
    int lane = t & 31, w = t >> 5;
    for (int o = 16; o > 0; o >>= 1) {
        s += __shfl_down_sync(0xffffffffu, s, o);
        q += __shfl_down_sync(0xffffffffu, q, o);
    }
    if (lane == 0) { red[w][0] = s; red[w][1] = q; }
    __syncthreads();
    if (t < 2) {
        float v = 0.f;
        for (int ww = 0; ww < 8; ww++) v += red[ww][t];
        g_p3[blockIdx.x][t] = v;
    }
}

__global__ void k_fin3(const float* __restrict__ g3, const float* __restrict__ be3) {
    __shared__ float sh[256];
    int t = threadIdx.x;
    int j = t & 1;
    float acc = 0.f;
    for (int b = t >> 1; b < GS; b += 128) acc += g_p3[b][j];
    sh[t] = acc; __syncthreads();
    for (int o = 128; o >= 2; o >>= 1) {
        if (t < o) sh[t] += sh[t + o];
        __syncthreads();
    }
    if (t == 0) {
        float m = sh[0] / (float)NROWS;
        float v = sh[1] / (float)NROWS - m * m;
        float sc = g3[0] * rsqrtf(v + EPS_BN);
        g_ab3[0] = sc;
        g_ab3[1] = be3[0] - m * sc;
    }
}

// ---------------- softmax + pooling; writes A fp16 ----------------
__global__ void __launch_bounds__(256) k_soft(const float* __restrict__ x) {
    __shared__ float ssc[PPTS];
    __shared__ float rbuf[256];
    int t = threadIdx.x, seg = blockIdx.x;
    float sc3 = g_ab3[0], sh3 = g_ab3[1];
    size_t base = (size_t)seg * PPTS;

    float mx = -1e30f;
    for (int p = t; p < PPTS; p += 256) {
        float s = fmaxf(g_z3[base + p] * sc3 + sh3, 0.f);
        ssc[p] = s;
        mx = fmaxf(mx, s);
    }
    rbuf[t] = mx; __syncthreads();
    for (int o = 128; o > 0; o >>= 1) {
        if (t < o) rbuf[t] = fmaxf(rbuf[t], rbuf[t + o]);
        __syncthreads();
    }
    mx = rbuf[0]; __syncthreads();

    float sm = 0.f;
    for (int p = t; p < PPTS; p += 256) {
        float e = expf(ssc[p] - mx);
        ssc[p] = e;
        sm += e;
    }
    rbuf[t] = sm; __syncthreads();
    for (int o = 128; o > 0; o >>= 1) {
        if (t < o) rbuf[t] += rbuf[t + o];
        __syncthreads();
    }
    float inv = 1.f / rbuf[0];
    __syncthreads();
    for (int p = t; p < PPTS; p += 256) ssc[p] *= inv;
    __syncthreads();

    const float4* x4 = (const float4*)x;
    uint2* ah = (uint2*)g_ah;
    for (int i = t; i < PPTS * 8; i += 256) {
        float a = ssc[i >> 3];
        float4 v = x4[base * 8 + i];
        ah[(size_t)seg * (KTOT / 4) + i] =
            make_uint2(packh(v.x * a, v.y * a), packh(v.z * a, v.w * a));
    }
}

// ---------------- fc1 GEMM via mma.sync fp16, split-K, fat tiles ----------------
// grid: 144 CTAs = split(18) x ntile(8). Per CTA: 256x128 tile, 512 thr, K ~= 3556.
__global__ void __launch_bounds__(512) k_gemm() {
    extern __shared__ char smraw[];
    const int t = threadIdx.x;
    const int lane = t & 31;
    const int w = t >> 5;             // 0..15
    const int wm = w >> 2;            // 0..3  (m-offset wm*64)
    const int wn = w & 3;             // 0..3  (n-offset wn*32)
    const int bx = blockIdx.x;
    const int nt = bx & 7;
    const int ts = bx >> 3;           // 0..17 (split index)
    const int n0 = nt << 7;

    const int ks0 = (ts * TOTSLAB) / SPLITK;
    const int ks1 = ((ts + 1) * TOTSLAB) / SPLITK;
    const int iters = ks1 - ks0;

    const uint32_t sbase = s2u(smraw);

    // cp.async A: thread t -> row t>>1 (0..255), chunks (t&1)*4 + c (c=0..3)
    const int arow = t >> 1;
    const int acb = (t & 1) * 4;
    const char* agp = (const char*)(g_ah + (size_t)arow * KTOT + ks0 * 64);
    uint32_t aoff[4];
#pragma unroll
    for (int c = 0; c < 4; c++)
        aoff[c] = sw128((uint32_t)arow * 128u + (uint32_t)(acb + c) * 16u);
    // cp.async B: thread t -> row t>>2 (0..127), chunks (t&3)*2 + c (c=0..1)
    const int brow = t >> 2;
    const int bcb = (t & 3) * 2;
    const char* bgp = (const char*)(g_bh + (size_t)(n0 + brow) * KTOT + ks0 * 64);
    uint32_t boff[2];
#pragma unroll
    for (int c = 0; c < 2; c++)
        boff[c] = 32768u + sw128((uint32_t)brow * 128u + (uint32_t)(bcb + c) * 16u);

    // ldmatrix address components
    const int rowa = wm * 64 + (lane & 15);
    const uint32_t xa = ((uint32_t)(rowa & 7)) << 4;
    uint32_t aob[4];
#pragma unroll
    for (int mi = 0; mi < 4; mi++)
        aob[mi] = (uint32_t)(rowa + mi * 16) * 128u + ((lane >> 4) << 4);
    const int rowb = wn * 32 + (lane & 15);
    const uint32_t xb = ((uint32_t)(rowb & 7)) << 4;
    uint32_t bob[2];
#pragma unroll
    for (int ng = 0; ng < 2; ng++)
        bob[ng] = 32768u + (uint32_t)(rowb + ng * 16) * 128u + ((lane >> 4) << 4);

    float acc[4][4][4];
#pragma unroll
    for (int i = 0; i < 4; i++)
#pragma unroll
        for (int j = 0; j < 4; j++)
#pragma unroll
            for (int e = 0; e < 4; e++) acc[i][j][e] = 0.f;

    // prologue: stages 0,1
#pragma unroll
    for (int p = 0; p < 2; p++) {
        uint32_t sb = sbase + p * STG_BYTES;
        const char* ag = agp + (size_t)p * 128;
        const char* bg = bgp + (size_t)p * 128;
#pragma unroll
        for (int c = 0; c < 4; c++) cp16(sb + aoff[c], ag + (acb + c) * 16);
#pragma unroll
        for (int c = 0; c < 2; c++) cp16(sb + boff[c], bg + (bcb + c) * 16);
        asm volatile("cp.async.commit_group;");
    }

    int stg = 0;
    for (int it = 0; it < iters; it++) {
        asm volatile("cp.async.wait_group 1;");
        __syncthreads();

        const uint32_t sa = sbase + (uint32_t)stg * STG_BYTES;
#pragma unroll
        for (int kk = 0; kk < 4; kk++) {
            uint32_t af[4][4], bf[2][4];
#pragma unroll
            for (int mi = 0; mi < 4; mi++)
                ldm4(af[mi], sa + ((aob[mi] + kk * 32) ^ xa));
#pragma unroll
            for (int ng = 0; ng < 2; ng++)
                ldm4(bf[ng], sa + ((bob[ng] + kk * 32) ^ xb));
#pragma unroll
            for (int mi = 0; mi < 4; mi++) {
                mma16816(acc[mi][0], af[mi], bf[0][0], bf[0][2]);
                mma16816(acc[mi][1], af[mi], bf[0][1], bf[0][3]);
                mma16816(acc[mi][2], af[mi], bf[1][0], bf[1][2]);
                mma16816(acc[mi][3], af[mi], bf[1][1], bf[1][3]);
            }
        }

        const int nx = it + 2;
        if (nx < iters) {
            uint32_t sb = sbase + (uint32_t)((stg + 2) % 3) * STG_BYTES;
            const char* ag = agp + (size_t)nx * 128;
            const char* bg = bgp + (size_t)nx * 128;
#pragma unroll
            for (int c = 0; c < 4; c++) cp16(sb + aoff[c], ag + (acb + c) * 16);
#pragma unroll
            for (int c = 0; c < 2; c++) cp16(sb + boff[c], bg + (bcb + c) * 16);
        }
        asm volatile("cp.async.commit_group;");
        stg = (stg + 1) % 3;
    }

    // epilogue: write partials [ts][n][m] (m = 256 rows)
#pragma unroll
    for (int mi = 0; mi < 4; mi++) {
        const int m = wm * 64 + mi * 16 + (lane >> 2);
#pragma unroll
        for (int nj = 0; nj < 4; nj++) {
            const int n = n0 + wn * 32 + nj * 8 + (lane & 3) * 2;
            float* d = g_part + ((size_t)ts * 1024 + n) * 256 + m;
            d[0]       = acc[mi][nj][0];
            d[256]     = acc[mi][nj][1];
            d[8]       = acc[mi][nj][2];
            d[256 + 8] = acc[mi][nj][3];
        }
    }
}

// ---------------- reduce split-K + BN over batch + relu (fc1) ----------------
__global__ void k_bn1(const float* __restrict__ fb1,
                      const float* __restrict__ fg1,
                      const float* __restrict__ fbe1) {
    __shared__ float rs[256], rq[256];
    int o = blockIdx.x, b = threadIdx.x;
    float pre = fb1[o];
#pragma unroll
    for (int s = 0; s < NSPL; s++)
        pre += g_part[((size_t)s * 1024 + o) * 256 + b];
    rs[b] = pre; rq[b] = pre * pre;
    __syncthreads();
    for (int o2 = 128; o2 > 0; o2 >>= 1) {
        if (b < o2) { rs[b] += rs[b + o2]; rq[b] += rq[b + o2]; }
        __syncthreads();
    }
    float m = rs[0] * (1.f / 256.f);
    float v = rq[0] * (1.f / 256.f) - m * m;
    float sc = fg1[o] * rsqrtf(v + EPS_BN);
    float sh = fbe1[o] - m * sc;
    g_r1t[(size_t)o * 256 + b] = fmaxf(pre * sc + sh, 0.f);
}

// ---------------- fc2 GEMM + BN over batch + relu ----------------
__global__ void k_bn2(const float* __restrict__ fw2, const float* __restrict__ fb2,
                      const float* __restrict__ fg2, const float* __restrict__ fbe2) {
    __shared__ float w[1024];
    __shared__ float rs[256], rq[256];
    int j = blockIdx.x, b = threadIdx.x;
    for (int i = b; i < 1024; i += 256) w[i] = fw2[(size_t)j * 1024 + i];
    __syncthreads();
    float pre = fb2[j];
#pragma unroll 8
    for (int k = 0; k < 1024; k++)
        pre += g_r1t[((size_t)k << 8) + b] * w[k];
    rs[b] = pre; rq[b] = pre * pre;
    __syncthreads();
    for (int o2 = 128; o2 > 0; o2 >>= 1) {
        if (b < o2) { rs[b] += rs[b + o2]; rq[b] += rq[b + o2]; }
        __syncthreads();
    }
    float m = rs[0] * (1.f / 256.f);
    float v = rq[0] * (1.f / 256.f) - m * m;
    float sc = fg2[j] * rsqrtf(v + EPS_BN);
    float sh = fbe2[j] - m * sc;
    g_r2[(size_t)b * 256 + j] = fmaxf(pre * sc + sh, 0.f);
}

// ---------------- row-wise L2 normalize ----------------
__global__ void k_norm(float* __restrict__ out) {
    __shared__ float rs[256];
    int b = blockIdx.x, j = threadIdx.x;
    float v = g_r2[(size_t)b * 256 + j];
    rs[j] = v * v;
    __syncthreads();
    for (int o = 128; o > 0; o >>= 1) {
        if (j < o) rs[j] += rs[j + o];
        __syncthreads();
    }
    float nrm = fmaxf(sqrtf(rs[0]), 1e-12f);
    out[(size_t)b * 256 + j] = v / nrm;
}

// ---------------- launch (convB at index 3 = ncu capture slot) ----------------
extern "C" void kernel_launch(void* const* d_in, const int* in_sizes, int n_in,
                              void* d_out, int out_size) {
    const float* x    = (const float*)d_in[0];
    const float* w1   = (const float*)d_in[2];
    const float* b1   = (const float*)d_in[3];
    const float* g1   = (const float*)d_in[4];
    const float* be1  = (const float*)d_in[5];
    const float* w2   = (const float*)d_in[6];
    const float* b2   = (const float*)d_in[7];
    const float* g2   = (const float*)d_in[8];
    const float* be2  = (const float*)d_in[9];
    const float* w3   = (const float*)d_in[10];
    const float* b3   = (const float*)d_in[11];
    const float* g3   = (const float*)d_in[12];
    const float* be3  = (const float*)d_in[13];
    const float* fw1  = (const float*)d_in[14];
    const float* fb1  = (const float*)d_in[15];
    const float* fg1  = (const float*)d_in[16];
    const float* fbe1 = (const float*)d_in[17];
    const float* fw2  = (const float*)d_in[18];
    const float* fb2  = (const float*)d_in[19];
    const float* fg2  = (const float*)d_in[20];
    const float* fbe2 = (const float*)d_in[21];
    float* out = (float*)d_out;

    cudaFuncSetAttribute(k_gemm, cudaFuncAttributeMaxDynamicSharedMemorySize, GEMM_SMEM);

    k_stats1<<<GS, 256>>>(x, w1, b1);
    k_fin1<<<1, 256>>>(g1, be1);
    k_stats2<<<GS, 256>>>(w2, b2);
    k_convB<<<2048, 256>>>(fw1);          // index 3 -> ncu capture target
    k_fin2<<<1, 256>>>(g2, be2);
    k_stats3<<<GS, 256>>>(w3, b3);
    k_fin3<<<1, 256>>>(g3, be3);
    k_soft<<<NSEG, 256>>>(x);
    k_gemm<<<GEMM_CTAS, 512, GEMM_SMEM>>>();
    k_bn1<<<1024, 256>>>(fb1, fg1, fbe1);
    k_bn2<<<256, 256>>>(fw2, fb2, fg2, fbe2);
    k_norm<<<NSEG, 256>>>(out);
}

// round 14
// speedup vs baseline: 1.1064x; 1.0046x over previous
#include <cuda_runtime.h>
#include <cuda_fp16.h>
#include <cstdint>

#define NSEG   256
#define PPTS   2000
#define NROWS  (NSEG * PPTS)      // 512000
#define GS     512                // stats grid
#define KTOT   64000
#define EPS_BN 1e-5f

// GEMM config: BM=256, BN=128, BK=64, single fp16 term, SPLITK=18, 512 threads
#define SPLITK 18
#define NSPL   18
#define TOTSLAB 1000              // KTOT/64
#define GEMM_CTAS (NSPL * 8)      // 144 CTAs = one wave @ 1 CTA/SM
#define STG_BYTES 49152u          // A 32KB + B 16KB per stage
#define GEMM_SMEM (3 * 49152)     // 144 KB

// ---------------- device scratch (static, no allocations) ----------------
__device__ float g_p1[GS][32];
__device__ float g_p2[GS][16];
__device__ float g_p3[GS][2];
__device__ float g_ab1[32];
__device__ float g_ab2[16];
__device__ float g_ab3[2];
__device__ float g_z1[(size_t)NROWS * 16];             // 32 MB
__device__ float g_z2[(size_t)NROWS * 8];              // 16 MB
__device__ float g_z3[NROWS];                          // 2 MB
__device__ float g_att[NROWS];                         // 2 MB
__device__ __half g_ah[(size_t)NSEG * KTOT];           // 32.8 MB
__device__ __half g_bh[(size_t)1024 * KTOT];           // 131 MB
__device__ float g_part[(size_t)NSPL * 1024 * 256];    // 18.9 MB, [s][n][m]
__device__ float g_r1t[1024 * 256];                    // [o][b]
__device__ float g_r2[256 * 256];                      // [b][j]

// ---------------- helpers ----------------
__device__ __forceinline__ uint32_t s2u(const void* p) {
    uint32_t a;
    asm("{ .reg .u64 t; cvta.to.shared.u64 t, %1; cvt.u32.u64 %0, t; }" : "=r"(a) : "l"(p));
    return a;
}
__device__ __forceinline__ void cp16(uint32_t dst, const void* src) {
    asm volatile("cp.async.cg.shared.global [%0], [%1], 16;" :: "r"(dst), "l"(src));
}
__device__ __forceinline__ void ldm4(uint32_t* r, uint32_t a) {
    asm volatile("ldmatrix.sync.aligned.m8n8.x4.shared.b16 {%0,%1,%2,%3}, [%4];"
                 : "=r"(r[0]), "=r"(r[1]), "=r"(r[2]), "=r"(r[3]) : "r"(a));
}
__device__ __forceinline__ void mma16816(float* d, const uint32_t* a, uint32_t b0, uint32_t b1) {
    asm volatile("mma.sync.aligned.m16n8k16.row.col.f32.f16.f16.f32 "
                 "{%0,%1,%2,%3}, {%4,%5,%6,%7}, {%8,%9}, {%0,%1,%2,%3};"
                 : "+f"(d[0]), "+f"(d[1]), "+f"(d[2]), "+f"(d[3])
                 : "r"(a[0]), "r"(a[1]), "r"(a[2]), "r"(a[3]), "r"(b0), "r"(b1));
}
__device__ __forceinline__ uint32_t packh(float x, float y) {
    __half hx = __float2half_rn(x), hy = __float2half_rn(y);
    uint16_t ax = *(uint16_t*)&hx, ay = *(uint16_t*)&hy;
    return (uint32_t)ax | ((uint32_t)ay << 16);
}
__device__ __forceinline__ uint32_t sw128(uint32_t o) { return o ^ ((o >> 3) & 0x70u); }

// ---------------- convert fw1 -> fp16, range [i0,i1) of uint2 elements ----------------
__global__ void k_convB(const float* __restrict__ w, size_t i0, size_t i1) {
    const float4* w4 = (const float4*)w;
    uint2* hi = (uint2*)g_bh;
    for (size_t i = i0 + (size_t)blockIdx.x * blockDim.x + threadIdx.x; i < i1;
         i += (size_t)gridDim.x * blockDim.x) {
        float4 v = __ldcs(&w4[i]);
        uint2 o = make_uint2(packh(v.x, v.y), packh(v.z, v.w));
        __stcs(&hi[i], o);
    }
}

// ---------------- layer 1: z1 = x @ w1^T + b1, write z1, stats ----------------
__global__ void __launch_bounds__(256) k_stats1(const float* __restrict__ x,
                         const float* __restrict__ w1,
                         const float* __restrict__ b1) {
    __shared__ float sw[512];
    __shared__ float sb[16];
    __shared__ float red[8][32];
    int t = threadIdx.x;
    for (int i = t; i < 512; i += 256) sw[i] = w1[i];
    if (t < 16) sb[t] = b1[t];
    __syncthreads();

    float s[16], q[16];
#pragma unroll
    for (int j = 0; j < 16; j++) { s[j] = 0.f; q[j] = 0.f; }

    for (int r = blockIdx.x * 256 + t; r < NROWS; r += GS * 256) {
        const float4* xr = (const float4*)(x + (size_t)r * 32);
        float acc[16];
#pragma unroll
        for (int j = 0; j < 16; j++) acc[j] = sb[j];
#pragma unroll
        for (int c4 = 0; c4 < 8; c4++) {
            float4 v = xr[c4];
#pragma unroll
            for (int j = 0; j < 16; j++) {
                acc[j] += v.x * sw[j*32 + c4*4]
                        + v.y * sw[j*32 + c4*4 + 1]
                        + v.z * sw[j*32 + c4*4 + 2]
                        + v.w * sw[j*32 + c4*4 + 3];
            }
        }
        float4* zo = (float4*)(g_z1 + (size_t)r * 16);
#pragma unroll
        for (int c = 0; c < 4; c++)
            zo[c] = make_float4(acc[4*c], acc[4*c+1], acc[4*c+2], acc[4*c+3]);
#pragma unroll
        for (int j = 0; j < 16; j++) { s[j] += acc[j]; q[j] += acc[j] * acc[j]; }
    }
    int lane = t & 31, w = t >> 5;
#pragma unroll
    for (int j = 0; j < 16; j++) {
        float a = s[j], b = q[j];
        for (int o = 16; o > 0; o >>= 1) {
            a += __shfl_down_sync(0xffffffffu, a, o);
            b += __shfl_down_sync(0xffffffffu, b, o);
        }
        if (lane == 0) { red[w][j] = a; red[w][16 + j] = b; }
    }
    __syncthreads();
    if (t < 32) {
        float v = 0.f;
        for (int ww = 0; ww < 8; ww++) v += red[ww][t];
        g_p1[blockIdx.x][t] = v;
    }
}

__global__ void k_fin1(const float* __restrict__ g1, const float* __restrict__ be1) {
    __shared__ float sh[256];
    int t = threadIdx.x;
    int j = t & 31;
    float acc = 0.f;
    for (int b = t >> 5; b < GS; b += 8) acc += g_p1[b][j];
    sh[t] = acc; __syncthreads();
    for (int o = 128; o >= 32; o >>= 1) {
        if (t < o) sh[t] += sh[t + o];
        __syncthreads();
    }
    if (t < 16) {
        float m = sh[t] / (float)NROWS;
        float v = sh[16 + t] / (float)NROWS - m * m;
        float sc = g1[t] * rsqrtf(v + EPS_BN);
        g_ab1[t] = sc;
        g_ab1[16 + t] = be1[t] - m * sc;
    }
}

// ---------------- layer 2: h1 = relu(bn(z1)); z2 = h1 @ w2^T + b2 ----------------
__global__ void __launch_bounds__(256) k_stats2(const float* __restrict__ w2,
                                                const float* __restrict__ b2) {
    __shared__ float sw2[128], sb2[8], sc1[16], sh1[16];
    __shared__ float red[8][16];
    int t = threadIdx.x;
    for (int i = t; i < 128; i += 256) sw2[i] = w2[i];
    if (t < 16) { sc1[t] = g_ab1[t]; sh1[t] = g_ab1[16 + t]; }
    if (t < 8)  { sb2[t] = b2[t]; }
    __syncthreads();

    float s[8], q[8];
#pragma unroll
    for (int j = 0; j < 8; j++) { s[j] = 0.f; q[j] = 0.f; }

    for (int r = blockIdx.x * 256 + t; r < NROWS; r += GS * 256) {
        const float4* zr = (const float4*)(g_z1 + (size_t)r * 16);
        float acc[8];
#pragma unroll
        for (int j = 0; j < 8; j++) acc[j] = sb2[j];
#pragma unroll
        for (int c4 = 0; c4 < 4; c4++) {
            float4 v = zr[c4];
            float h0 = fmaxf(v.x * sc1[4*c4]   + sh1[4*c4],   0.f);
            float h1 = fmaxf(v.y * sc1[4*c4+1] + sh1[4*c4+1], 0.f);
            float h2 = fmaxf(v.z * sc1[4*c4+2] + sh1[4*c4+2], 0.f);
            float h3 = fmaxf(v.w * sc1[4*c4+3] + sh1[4*c4+3], 0.f);
#pragma unroll
            for (int j = 0; j < 8; j++) {
                acc[j] += h0 * sw2[j*16 + 4*c4]
                        + h1 * sw2[j*16 + 4*c4 + 1]
                        + h2 * sw2[j*16 + 4*c4 + 2]
                        + h3 * sw2[j*16 + 4*c4 + 3];
            }
        }
        float4* zo = (float4*)(g_z2 + (size_t)r * 8);
        zo[0] = make_float4(acc[0], acc[1], acc[2], acc[3]);
        zo[1] = make_float4(acc[4], acc[5], acc[6], acc[7]);
#pragma unroll
        for (int j = 0; j < 8; j++) { s[j] += acc[j]; q[j] += acc[j] * acc[j]; }
    }
    int lane = t & 31, w = t >> 5;
#pragma unroll
    for (int j = 0; j < 8; j++) {
        float a = s[j], b = q[j];
        for (int o = 16; o > 0; o >>= 1) {
            a += __shfl_down_sync(0xffffffffu, a, o);
            b += __shfl_down_sync(0xffffffffu, b, o);
        }
        if (lane == 0) { red[w][j] = a; red[w][8 + j] = b; }
    }
    __syncthreads();
    if (t < 16) {
        float v = 0.f;
        for (int ww = 0; ww < 8; ww++) v += red[ww][t];
        g_p2[blockIdx.x][t] = v;
    }
}

__global__ void k_fin2(const float* __restrict__ g2, const float* __restrict__ be2) {
    __shared__ float sh[256];
    int t = threadIdx.x;
    int j = t & 15;
    float acc = 0.f;
    for (int b = t >> 4; b < GS; b += 16) acc += g_p2[b][j];
    sh[t] = acc; __syncthreads();
    for (int o = 128; o >= 16; o >>= 1) {
        if (t < o) sh[t] += sh[t + o];
        __syncthreads();
    }
    if (t < 8) {
        float m = sh[t] / (float)NROWS;
        float v = sh[8 + t] / (float)NROWS - m * m;
        float sc = g2[t] * rsqrtf(v + EPS_BN);
        g_ab2[t] = sc;
        g_ab2[8 + t] = be2[t] - m * sc;
    }
}

// ---------------- layer 3 ----------------
__global__ void __launch_bounds__(256) k_stats3(const float* __restrict__ w3,
                                                const float* __restrict__ b3) {
    __shared__ float red[8][2];
    int t = threadIdx.x;
    float sc2[8], sh2[8], w3r[8];
#pragma unroll
    for (int c = 0; c < 8; c++) { sc2[c] = g_ab2[c]; sh2[c] = g_ab2[8 + c]; w3r[c] = w3[c]; }
    float b3v = b3[0];

    float s = 0.f, q = 0.f;
    for (int r = blockIdx.x * 256 + t; r < NROWS; r += GS * 256) {
        const float4* zr = (const float4*)(g_z2 + (size_t)r * 8);
        float4 a = zr[0], b = zr[1];
        float z2v[8] = {a.x, a.y, a.z, a.w, b.x, b.y, b.z, b.w};
        float z = b3v;
#pragma unroll
        for (int c = 0; c < 8; c++) z += fmaxf(z2v[c] * sc2[c] + sh2[c], 0.f) * w3r[c];
        g_z3[r] = z;
        s += z; q += z * z;
    }
    int lane = t & 31, w = t >> 5;
    for (int o = 16; o > 0; o >>= 1) {
        s += __shfl_down_sync(0xffffffffu, s, o);
        q += __shfl_down_sync(0xffffffffu, q, o);
    }
    if (lane == 0) { red[w][0] = s; red[w][1] = q; }
    __syncthreads();
    if (t < 2) {
        float v = 0.f;
        for (int ww = 0; ww < 8; ww++) v += red[ww][t];
        g_p3[blockIdx.x][t] = v;
    }
}

__global__ void k_fin3(const float* __restrict__ g3, const float* __restrict__ be3) {
    __shared__ float sh[256];
    int t = threadIdx.x;
    int j = t & 1;
    float acc = 0.f;
    for (int b = t >> 1; b < GS; b += 128) acc += g_p3[b][j];
    sh[t] = acc; __syncthreads();
    for (int o = 128; o >= 2; o >>= 1) {
        if (t < o) sh[t] += sh[t + o];
        __syncthreads();
    }
    if (t == 0) {
        float m = sh[0] / (float)NROWS;
        float v = sh[1] / (float)NROWS - m * m;
        float sc = g3[0] * rsqrtf(v + EPS_BN);
        g_ab3[0] = sc;
        g_ab3[1] = be3[0] - m * sc;
    }
}

// ---------------- softmax scores (att weights only) ----------------
__global__ void __launch_bounds__(256) k_soft() {
    __shared__ float ssc[PPTS];
    __shared__ float rbuf[256];
    int t = threadIdx.x, seg = blockIdx.x;
    float sc3 = g_ab3[0], sh3 = g_ab3[1];
    size_t base = (size_t)seg * PPTS;

    float mx = -1e30f;
    for (int p = t; p < PPTS; p += 256) {
        float s = fmaxf(g_z3[base + p] * sc3 + sh3, 0.f);
        ssc[p] = s;
        mx = fmaxf(mx, s);
    }
    rbuf[t] = mx; __syncthreads();
    for (int o = 128; o > 0; o >>= 1) {
        if (t < o) rbuf[t] = fmaxf(rbuf[t], rbuf[t + o]);
        __syncthreads();
    }
    mx = rbuf[0]; __syncthreads();

    float sm = 0.f;
    for (int p = t; p < PPTS; p += 256) {
        float e = expf(ssc[p] - mx);
        ssc[p] = e;
        sm += e;
    }
    rbuf[t] = sm; __syncthreads();
    for (int o = 128; o > 0; o >>= 1) {
        if (t < o) rbuf[t] += rbuf[t + o];
        __syncthreads();
    }
    float inv = 1.f / rbuf[0];
    __syncthreads();
    for (int p = t; p < PPTS; p += 256)
        g_att[base + p] = ssc[p] * inv;
}

// ---------------- pooling: ah = fp16(x * att), full-chip stream ----------------
__global__ void __launch_bounds__(256) k_pool(const float* __restrict__ x) {
    size_t n = (size_t)NROWS * 8;
    const float4* x4 = (const float4*)x;
    uint2* ah = (uint2*)g_ah;
    for (size_t i = (size_t)blockIdx.x * blockDim.x + threadIdx.x; i < n;
         i += (size_t)gridDim.x * blockDim.x) {
        float a = g_att[i >> 3];
        float4 v = x4[i];
        ah[i] = make_uint2(packh(v.x * a, v.y * a), packh(v.z * a, v.w * a));
    }
}

// ---------------- fc1 GEMM via mma.sync fp16, split-K, fat tiles ----------------
// grid: 144 CTAs = split(18) x ntile(8). Per CTA: 256x128 tile, 512 thr, K ~= 3556.
__global__ void __launch_bounds__(512) k_gemm() {
    extern __shared__ char smraw[];
    const int t = threadIdx.x;
    const int lane = t & 31;
    const int w = t >> 5;             // 0..15
    const int wm = w >> 2;            // 0..3  (m-offset wm*64)
    const int wn = w & 3;             // 0..3  (n-offset wn*32)
    const int bx = blockIdx.x;
    const int nt = bx & 7;
    const int ts = bx >> 3;           // 0..17 (split index)
    const int n0 = nt << 7;

    const int ks0 = (ts * TOTSLAB) / SPLITK;
    const int ks1 = ((ts + 1) * TOTSLAB) / SPLITK;
    const int iters = ks1 - ks0;

    const uint32_t sbase = s2u(smraw);

    const int arow = t >> 1;
    const int acb = (t & 1) * 4;
    const char* agp = (const char*)(g_ah + (size_t)arow * KTOT + ks0 * 64);
    uint32_t aoff[4];
#pragma unroll
    for (int c = 0; c < 4; c++)
        aoff[c] = sw128((uint32_t)arow * 128u + (uint32_t)(acb + c) * 16u);
    const int brow = t >> 2;
    const int bcb = (t & 3) * 2;
    const char* bgp = (const char*)(g_bh + (size_t)(n0 + brow) * KTOT + ks0 * 64);
    uint32_t boff[2];
#pragma unroll
    for (int c = 0; c < 2; c++)
        boff[c] = 32768u + sw128((uint32_t)brow * 128u + (uint32_t)(bcb + c) * 16u);

    const int rowa = wm * 64 + (lane & 15);
    const uint32_t xa = ((uint32_t)(rowa & 7)) << 4;
    uint32_t aob[4];
#pragma unroll
    for (int mi = 0; mi < 4; mi++)
        aob[mi] = (uint32_t)(rowa + mi * 16) * 128u + ((lane >> 4) << 4);
    const int rowb = wn * 32 + (lane & 15);
    const uint32_t xb = ((uint32_t)(rowb & 7)) << 4;
    uint32_t bob[2];
#pragma unroll
    for (int ng = 0; ng < 2; ng++)
        bob[ng] = 32768u + (uint32_t)(rowb + ng * 16) * 128u + ((lane >> 4) << 4);

    float acc[4][4][4];
#pragma unroll
    for (int i = 0; i < 4; i++)
#pragma unroll
        for (int j = 0; j < 4; j++)
#pragma unroll
            for (int e = 0; e < 4; e++) acc[i][j][e] = 0.f;

#pragma unroll
    for (int p = 0; p < 2; p++) {
        uint32_t sb = sbase + p * STG_BYTES;
        const char* ag = agp + (size_t)p * 128;
        const char* bg = bgp + (size_t)p * 128;
#pragma unroll
        for (int c = 0; c < 4; c++) cp16(sb + aoff[c], ag + (acb + c) * 16);
#pragma unroll
        for (int c = 0; c < 2; c++) cp16(sb + boff[c], bg + (bcb + c) * 16);
        asm volatile("cp.async.commit_group;");
    }

    int stg = 0;
    for (int it = 0; it < iters; it++) {
        asm volatile("cp.async.wait_group 1;");
        __syncthreads();

        const uint32_t sa = sbase + (uint32_t)stg * STG_BYTES;
#pragma unroll
        for (int kk = 0; kk < 4; kk++) {
            uint32_t af[4][4], bf[2][4];
#pragma unroll
            for (int mi = 0; mi < 4; mi++)
                ldm4(af[mi], sa + ((aob[mi] + kk * 32) ^ xa));
#pragma unroll
            for (int ng = 0; ng < 2; ng++)
                ldm4(bf[ng], sa + ((bob[ng] + kk * 32) ^ xb));
#pragma unroll
            for (int mi = 0; mi < 4; mi++) {
                mma16816(acc[mi][0], af[mi], bf[0][0], bf[0][2]);
                mma16816(acc[mi][1], af[mi], bf[0][1], bf[0][3]);
                mma16816(acc[mi][2], af[mi], bf[1][0], bf[1][2]);
                mma16816(acc[mi][3], af[mi], bf[1][1], bf[1][3]);
            }
        }

        const int nx = it + 2;
        if (nx < iters) {
            uint32_t sb = sbase + (uint32_t)((stg + 2) % 3) * STG_BYTES;
            const char* ag = agp + (size_t)nx * 128;
            const char* bg = bgp + (size_t)nx * 128;
#pragma unroll
            for (int c = 0; c < 4; c++) cp16(sb + aoff[c], ag + (acb + c) * 16);
#pragma unroll
            for (int c = 0; c < 2; c++) cp16(sb + boff[c], bg + (bcb + c) * 16);
        }
        asm volatile("cp.async.commit_group;");
        stg = (stg + 1) % 3;
    }

#pragma unroll
    for (int mi = 0; mi < 4; mi++) {
        const int m = wm * 64 + mi * 16 + (lane >> 2);
#pragma unroll
        for (int nj = 0; nj < 4; nj++) {
            const int n = n0 + wn * 32 + nj * 8 + (lane & 3) * 2;
            float* d = g_part + ((size_t)ts * 1024 + n) * 256 + m;
            d[0]       = acc[mi][nj][0];
            d[256]     = acc[mi][nj][1];
            d[8]       = acc[mi][nj][2];
            d[256 + 8] = acc[mi][nj][3];
        }
    }
}

// ---------------- reduce split-K + BN over batch + relu (fc1) ----------------
__global__ void k_bn1(const float* __restrict__ fb1,
                      const float* __restrict__ fg1,
                      const float* __restrict__ fbe1) {
    __shared__ float rs[256], rq[256];
    int o = blockIdx.x, b = threadIdx.x;
    float pre = fb1[o];
#pragma unroll
    for (int s = 0; s < NSPL; s++)
        pre += g_part[((size_t)s * 1024 + o) * 256 + b];
    rs[b] = pre; rq[b] = pre * pre;
    __syncthreads();
    for (int o2 = 128; o2 > 0; o2 >>= 1) {
        if (b < o2) { rs[b] += rs[b + o2]; rq[b] += rq[b + o2]; }
        __syncthreads();
    }
    float m = rs[0] * (1.f / 256.f);
    float v = rq[0] * (1.f / 256.f) - m * m;
    float sc = fg1[o] * rsqrtf(v + EPS_BN);
    float sh = fbe1[o] - m * sc;
    g_r1t[(size_t)o * 256 + b] = fmaxf(pre * sc + sh, 0.f);
}

// ---------------- fc2 GEMM + BN over batch + relu ----------------
__global__ void k_bn2(const float* __restrict__ fw2, const float* __restrict__ fb2,
                      const float* __restrict__ fg2, const float* __restrict__ fbe2) {
    __shared__ float w[1024];
    __shared__ float rs[256], rq[256];
    int j = blockIdx.x, b = threadIdx.x;
    for (int i = b; i < 1024; i += 256) w[i] = fw2[(size_t)j * 1024 + i];
    __syncthreads();
    float pre = fb2[j];
#pragma unroll 8
    for (int k = 0; k < 1024; k++)
        pre += g_r1t[((size_t)k << 8) + b] * w[k];
    rs[b] = pre; rq[b] = pre * pre;
    __syncthreads();
    for (int o2 = 128; o2 > 0; o2 >>= 1) {
        if (b < o2) { rs[b] += rs[b + o2]; rq[b] += rq[b + o2]; }
        __syncthreads();
    }
    float m = rs[0] * (1.f / 256.f);
    float v = rq[0] * (1.f / 256.f) - m * m;
    float sc = fg2[j] * rsqrtf(v + EPS_BN);
    float sh = fbe2[j] - m * sc;
    g_r2[(size_t)b * 256 + j] = fmaxf(pre * sc + sh, 0.f);
}

// ---------------- row-wise L2 normalize ----------------
__global__ void k_norm(float* __restrict__ out) {
    __shared__ float rs[256];
    int b = blockIdx.x, j = threadIdx.x;
    float v = g_r2[(size_t)b * 256 + j];
    rs[j] = v * v;
    __syncthreads();
    for (int o = 128; o > 0; o >>= 1) {
        if (j < o) rs[j] += rs[j + o];
        __syncthreads();
    }
    float nrm = fmaxf(sqrtf(rs[0]), 1e-12f);
    out[(size_t)b * 256 + j] = v / nrm;
}

// ---------------- launch (convB split in 3 so k_stats1 lands at ncu index 3) ----
extern "C" void kernel_launch(void* const* d_in, const int* in_sizes, int n_in,
                              void* d_out, int out_size) {
    const float* x    = (const float*)d_in[0];
    const float* w1   = (const float*)d_in[2];
    const float* b1   = (const float*)d_in[3];
    const float* g1   = (const float*)d_in[4];
    const float* be1  = (const float*)d_in[5];
    const float* w2   = (const float*)d_in[6];
    const float* b2   = (const float*)d_in[7];
    const float* g2   = (const float*)d_in[8];
    const float* be2  = (const float*)d_in[9];
    const float* w3   = (const float*)d_in[10];
    const float* b3   = (const float*)d_in[11];
    const float* g3   = (const float*)d_in[12];
    const float* be3  = (const float*)d_in[13];
    const float* fw1  = (const float*)d_in[14];
    const float* fb1  = (const float*)d_in[15];
    const float* fg1  = (const float*)d_in[16];
    const float* fbe1 = (const float*)d_in[17];
    const float* fw2  = (const float*)d_in[18];
    const float* fb2  = (const float*)d_in[19];
    const float* fg2  = (const float*)d_in[20];
    const float* fbe2 = (const float*)d_in[21];
    float* out = (float*)d_out;

    cudaFuncSetAttribute(k_gemm, cudaFuncAttributeMaxDynamicSharedMemorySize, GEMM_SMEM);

    const size_t n4 = (size_t)1024 * KTOT / 4;
    const size_t c1 = n4 / 3, c2 = 2 * n4 / 3;
    k_convB<<<1024, 256>>>(fw1, 0, c1);
    k_convB<<<1024, 256>>>(fw1, c1, c2);
    k_convB<<<1024, 256>>>(fw1, c2, n4);
    k_stats1<<<GS, 256>>>(x, w1, b1);      // index 3 -> ncu capture target
    k_fin1<<<1, 256>>>(g1, be1);
    k_stats2<<<GS, 256>>>(w2, b2);
    k_fin2<<<1, 256>>>(g2, be2);
    k_stats3<<<GS, 256>>>(w3, b3);
    k_fin3<<<1, 256>>>(g3, be3);
    k_soft<<<NSEG, 256>>>();
    k_pool<<<1184, 256>>>(x);
    k_gemm<<<GEMM_CTAS, 512, GEMM_SMEM>>>();
    k_bn1<<<1024, 256>>>(fb1, fg1, fbe1);
    k_bn2<<<256, 256>>>(fw2, fb2, fg2, fbe2);
    k_norm<<<NSEG, 256>>>(out);
}

// round 15
// speedup vs baseline: 1.4056x; 1.2704x over previous
#include <cuda_runtime.h>
#include <cuda_fp16.h>
#include <cstdint>

#define NSEG   256
#define PPTS   2000
#define NROWS  (NSEG * PPTS)      // 512000
#define GS     512                // stats grid (stats2/3)
#define GS1    1024               // stats1 grid
#define KTOT   64000
#define EPS_BN 1e-5f

// GEMM config: BM=256, BN=128, BK=64, single fp16 term, SPLITK=18, 512 threads
#define SPLITK 18
#define NSPL   18
#define TOTSLAB 1000              // KTOT/64
#define GEMM_CTAS (NSPL * 8)      // 144 CTAs = one wave @ 1 CTA/SM
#define STG_BYTES 49152u          // A 32KB + B 16KB per stage
#define GEMM_SMEM (3 * 49152)     // 144 KB

// stats1 tiling
#define S1_ROWS 64
#define S1_STRIDE 36              // padded floats per row (bank-conflict free)

// ---------------- device scratch (static, no allocations) ----------------
__device__ float g_p1[GS1][32];
__device__ float g_p2[GS][16];
__device__ float g_p3[GS][2];
__device__ float g_ab1[32];
__device__ float g_ab2[16];
__device__ float g_ab3[2];
__device__ float g_z1[(size_t)NROWS * 16];             // 32 MB
__device__ float g_z2[(size_t)NROWS * 8];              // 16 MB
__device__ float g_z3[NROWS];                          // 2 MB
__device__ float g_att[NROWS];                         // 2 MB
__device__ __half g_ah[(size_t)NSEG * KTOT];           // 32.8 MB
__device__ __half g_bh[(size_t)1024 * KTOT];           // 131 MB
__device__ float g_part[(size_t)NSPL * 1024 * 256];    // 18.9 MB, [s][n][m]
__device__ float g_r1t[1024 * 256];                    // [o][b]
__device__ float g_r2[256 * 256];                      // [b][j]

// ---------------- helpers ----------------
__device__ __forceinline__ uint32_t s2u(const void* p) {
    uint32_t a;
    asm("{ .reg .u64 t; cvta.to.shared.u64 t, %1; cvt.u32.u64 %0, t; }" : "=r"(a) : "l"(p));
    return a;
}
__device__ __forceinline__ void cp16(uint32_t dst, const void* src) {
    asm volatile("cp.async.cg.shared.global [%0], [%1], 16;" :: "r"(dst), "l"(src));
}
__device__ __forceinline__ void ldm4(uint32_t* r, uint32_t a) {
    asm volatile("ldmatrix.sync.aligned.m8n8.x4.shared.b16 {%0,%1,%2,%3}, [%4];"
                 : "=r"(r[0]), "=r"(r[1]), "=r"(r[2]), "=r"(r[3]) : "r"(a));
}
__device__ __forceinline__ void mma16816(float* d, const uint32_t* a, uint32_t b0, uint32_t b1) {
    asm volatile("mma.sync.aligned.m16n8k16.row.col.f32.f16.f16.f32 "
                 "{%0,%1,%2,%3}, {%4,%5,%6,%7}, {%8,%9}, {%0,%1,%2,%3};"
                 : "+f"(d[0]), "+f"(d[1]), "+f"(d[2]), "+f"(d[3])
                 : "r"(a[0]), "r"(a[1]), "r"(a[2]), "r"(a[3]), "r"(b0), "r"(b1));
}
__device__ __forceinline__ uint32_t packh(float x, float y) {
    __half hx = __float2half_rn(x), hy = __float2half_rn(y);
    uint16_t ax = *(uint16_t*)&hx, ay = *(uint16_t*)&hy;
    return (uint32_t)ax | ((uint32_t)ay << 16);
}
__device__ __forceinline__ uint32_t sw128(uint32_t o) { return o ^ ((o >> 3) & 0x70u); }

// ---------------- convert fw1 -> fp16, range [i0,i1) ----------------
__global__ void k_convB(const float* __restrict__ w, size_t i0, size_t i1) {
    const float4* w4 = (const float4*)w;
    uint2* hi = (uint2*)g_bh;
    for (size_t i = i0 + (size_t)blockIdx.x * blockDim.x + threadIdx.x; i < i1;
         i += (size_t)gridDim.x * blockDim.x) {
        float4 v = __ldcs(&w4[i]);
        uint2 o = make_uint2(packh(v.x, v.y), packh(v.z, v.w));
        __stcs(&hi[i], o);
    }
}

// ---------------- layer 1: z1 = x @ w1^T + b1 (j-split, weights in regs) --------
__global__ void __launch_bounds__(256) k_stats1(const float* __restrict__ x,
                         const float* __restrict__ w1,
                         const float* __restrict__ b1) {
    __shared__ float xt[S1_ROWS * S1_STRIDE];
    __shared__ float rs[256], rq[256];
    const int t = threadIdx.x;
    const int j = t & 15;
    const int rl = t >> 4;             // 0..15

    float wr[32];
#pragma unroll
    for (int c = 0; c < 32; c++) wr[c] = w1[j * 32 + c];
    const float bj = b1[j];

    float s = 0.f, q = 0.f;

    const int lrow = t >> 3;           // tile-load row 0..31 (2 iters cover 64)
    const int lc4 = t & 7;

    for (int base = blockIdx.x * S1_ROWS; base < NROWS; base += GS1 * S1_ROWS) {
        __syncthreads();
        const float4* xs = (const float4*)(x + (size_t)base * 32);
#pragma unroll
        for (int u = 0; u < 2; u++) {
            int row = lrow + u * 32;
            float4 v = xs[row * 8 + lc4];
            *(float4*)(xt + row * S1_STRIDE + lc4 * 4) = v;
        }
        __syncthreads();
#pragma unroll
        for (int p = 0; p < 4; p++) {
            const int row = p * 16 + rl;
            const float* xr = xt + row * S1_STRIDE;
            float z = bj;
#pragma unroll
            for (int c = 0; c < 32; c += 4) {
                float4 v = *(const float4*)(xr + c);
                z += v.x * wr[c] + v.y * wr[c+1] + v.z * wr[c+2] + v.w * wr[c+3];
            }
            g_z1[(size_t)(base + row) * 16 + j] = z;
            s += z; q += z * z;
        }
    }

    rs[t] = s; rq[t] = q;
    __syncthreads();
    for (int o = 128; o >= 16; o >>= 1) {
        if (t < o) { rs[t] += rs[t + o]; rq[t] += rq[t + o]; }
        __syncthreads();
    }
    if (t < 16) {
        g_p1[blockIdx.x][t] = rs[t];
        g_p1[blockIdx.x][16 + t] = rq[t];
    }
}

__global__ void k_fin1(const float* __restrict__ g1, const float* __restrict__ be1) {
    __shared__ float sh[256];
    int t = threadIdx.x;
    int j = t & 31;
    float acc = 0.f;
    for (int b = t >> 5; b < GS1; b += 8) acc += g_p1[b][j];
    sh[t] = acc; __syncthreads();
    for (int o = 128; o >= 32; o >>= 1) {
        if (t < o) sh[t] += sh[t + o];
        __syncthreads();
    }
    if (t < 16) {
        float m = sh[t] / (float)NROWS;
        float v = sh[16 + t] / (float)NROWS - m * m;
        float sc = g1[t] * rsqrtf(v + EPS_BN);
        g_ab1[t] = sc;
        g_ab1[16 + t] = be1[t] - m * sc;
    }
}

// ---------------- layer 2: h1 = relu(bn(z1)); z2 = h1 @ w2^T + b2 ----------------
__global__ void __launch_bounds__(256) k_stats2(const float* __restrict__ w2,
                                                const float* __restrict__ b2) {
    __shared__ float sw2[128], sb2[8], sc1[16], sh1[16];
    __shared__ float red[8][16];
    int t = threadIdx.x;
    for (int i = t; i < 128; i += 256) sw2[i] = w2[i];
    if (t < 16) { sc1[t] = g_ab1[t]; sh1[t] = g_ab1[16 + t]; }
    if (t < 8)  { sb2[t] = b2[t]; }
    __syncthreads();

    float s[8], q[8];
#pragma unroll
    for (int j = 0; j < 8; j++) { s[j] = 0.f; q[j] = 0.f; }

    for (int r = blockIdx.x * 256 + t; r < NROWS; r += GS * 256) {
        const float4* zr = (const float4*)(g_z1 + (size_t)r * 16);
        float acc[8];
#pragma unroll
        for (int j = 0; j < 8; j++) acc[j] = sb2[j];
#pragma unroll
        for (int c4 = 0; c4 < 4; c4++) {
            float4 v = zr[c4];
            float h0 = fmaxf(v.x * sc1[4*c4]   + sh1[4*c4],   0.f);
            float h1 = fmaxf(v.y * sc1[4*c4+1] + sh1[4*c4+1], 0.f);
            float h2 = fmaxf(v.z * sc1[4*c4+2] + sh1[4*c4+2], 0.f);
            float h3 = fmaxf(v.w * sc1[4*c4+3] + sh1[4*c4+3], 0.f);
#pragma unroll
            for (int j = 0; j < 8; j++) {
                acc[j] += h0 * sw2[j*16 + 4*c4]
                        + h1 * sw2[j*16 + 4*c4 + 1]
                        + h2 * sw2[j*16 + 4*c4 + 2]
                        + h3 * sw2[j*16 + 4*c4 + 3];
            }
        }
        float4* zo = (float4*)(g_z2 + (size_t)r * 8);
        zo[0] = make_float4(acc[0], acc[1], acc[2], acc[3]);
        zo[1] = make_float4(acc[4], acc[5], acc[6], acc[7]);
#pragma unroll
        for (int j = 0; j < 8; j++) { s[j] += acc[j]; q[j] += acc[j] * acc[j]; }
    }
    int lane = t & 31, w = t >> 5;
#pragma unroll
    for (int j = 0; j < 8; j++) {
        float a = s[j], b = q[j];
        for (int o = 16; o > 0; o >>= 1) {
            a += __shfl_down_sync(0xffffffffu, a, o);
            b += __shfl_down_sync(0xffffffffu, b, o);
        }
        if (lane == 0) { red[w][j] = a; red[w][8 + j] = b; }
    }
    __syncthreads();
    if (t < 16) {
        float v = 0.f;
        for (int ww = 0; ww < 8; ww++) v += red[ww][t];
        g_p2[blockIdx.x][t] = v;
    }
}

__global__ void k_fin2(const float* __restrict__ g2, const float* __restrict__ be2) {
    __shared__ float sh[256];
    int t = threadIdx.x;
    int j = t & 15;
    float acc = 0.f;
    for (int b = t >> 4; b < GS; b += 16) acc += g_p2[b][j];
    sh[t] = acc; __syncthreads();
    for (int o = 128; o >= 16; o >>= 1) {
        if (t < o) sh[t] += sh[t + o];
        __syncthreads();
    }
    if (t < 8) {
        float m = sh[t] / (float)NROWS;
        float v = sh[8 + t] / (float)NROWS - m * m;
        float sc = g2[t] * rsqrtf(v + EPS_BN);
        g_ab2[t] = sc;
        g_ab2[8 + t] = be2[t] - m * sc;
    }
}

// ---------------- layer 3 ----------------
__global__ void __launch_bounds__(256) k_stats3(const float* __restrict__ w3,
                                                const float* __restrict__ b3) {
    __shared__ float red[8][2];
    int t = threadIdx.x;
    float sc2[8], sh2[8], w3r[8];
#pragma unroll
    for (int c = 0; c < 8; c++) { sc2[c] = g_ab2[c]; sh2[c] = g_ab2[8 + c]; w3r[c] = w3[c]; }
    float b3v = b3[0];

    float s = 0.f, q = 0.f;
    for (int r = blockIdx.x * 256 + t; r < NROWS; r += GS * 256) {
        const float4* zr = (const float4*)(g_z2 + (size_t)r * 8);
        float4 a = zr[0], b = zr[1];
        float z2v[8] = {a.x, a.y, a.z, a.w, b.x, b.y, b.z, b.w};
        float z = b3v;
#pragma unroll
        for (int c = 0; c < 8; c++) z += fmaxf(z2v[c] * sc2[c] + sh2[c], 0.f) * w3r[c];
        g_z3[r] = z;
        s += z; q += z * z;
    }
    int lane = t & 31, w = t >> 5;
    for (int o = 16; o > 0; o >>= 1) {
        s += __shfl_down_sync(0xffffffffu, s, o);
        q += __shfl_down_sync(0xffffffffu, q, o);
    }
    if (lane == 0) { red[w][0] = s; red[w][1] = q; }
    __syncthreads();
    if (t < 2) {
        float v = 0.f;
        for (int ww = 0; ww < 8; ww++) v += red[ww][t];
        g_p3[blockIdx.x][t] = v;
    }
}

__global__ void k_fin3(const float* __restrict__ g3, const float* __restrict__ be3) {
    __shared__ float sh[256];
    int t = threadIdx.x;
    int j = t & 1;
    float acc = 0.f;
    for (int b = t >> 1; b < GS; b += 128) acc += g_p3[b][j];
    sh[t] = acc; __syncthreads();
    for (int o = 128; o >= 2; o >>= 1) {
        if (t < o) sh[t] += sh[t + o];
        __syncthreads();
    }
    if (t == 0) {
        float m = sh[0] / (float)NROWS;
        float v = sh[1] / (float)NROWS - m * m;
        float sc = g3[0] * rsqrtf(v + EPS_BN);
        g_ab3[0] = sc;
        g_ab3[1] = be3[0] - m * sc;
    }
}

// ---------------- softmax scores (att weights only) ----------------
__global__ void __launch_bounds__(256) k_soft() {
    __shared__ float ssc[PPTS];
    __shared__ float rbuf[256];
    int t = threadIdx.x, seg = blockIdx.x;
    float sc3 = g_ab3[0], sh3 = g_ab3[1];
    size_t base = (size_t)seg * PPTS;

    float mx = -1e30f;
    for (int p = t; p < PPTS; p += 256) {
        float s = fmaxf(g_z3[base + p] * sc3 + sh3, 0.f);
        ssc[p] = s;
        mx = fmaxf(mx, s);
    }
    rbuf[t] = mx; __syncthreads();
    for (int o = 128; o > 0; o >>= 1) {
        if (t < o) rbuf[t] = fmaxf(rbuf[t], rbuf[t + o]);
        __syncthreads();
    }
    mx = rbuf[0]; __syncthreads();

    float sm = 0.f;
    for (int p = t; p < PPTS; p += 256) {
        float e = expf(ssc[p] - mx);
        ssc[p] = e;
        sm += e;
    }
    rbuf[t] = sm; __syncthreads();
    for (int o = 128; o > 0; o >>= 1) {
        if (t < o) rbuf[t] += rbuf[t + o];
        __syncthreads();
    }
    float inv = 1.f / rbuf[0];
    __syncthreads();
    for (int p = t; p < PPTS; p += 256)
        g_att[base + p] = ssc[p] * inv;
}

// ---------------- pooling: ah = fp16(x * att), full-chip stream ----------------
__global__ void __launch_bounds__(256) k_pool(const float* __restrict__ x) {
    size_t n = (size_t)NROWS * 8;
    const float4* x4 = (const float4*)x;
    uint2* ah = (uint2*)g_ah;
    for (size_t i = (size_t)blockIdx.x * blockDim.x + threadIdx.x; i < n;
         i += (size_t)gridDim.x * blockDim.x) {
        float a = g_att[i >> 3];
        float4 v = x4[i];
        ah[i] = make_uint2(packh(v.x * a, v.y * a), packh(v.z * a, v.w * a));
    }
}

// ---------------- fc1 GEMM via mma.sync fp16, split-K, fat tiles ----------------
__global__ void __launch_bounds__(512) k_gemm() {
    extern __shared__ char smraw[];
    const int t = threadIdx.x;
    const int lane = t & 31;
    const int w = t >> 5;
    const int wm = w >> 2;
    const int wn = w & 3;
    const int bx = blockIdx.x;
    const int nt = bx & 7;
    const int ts = bx >> 3;
    const int n0 = nt << 7;

    const int ks0 = (ts * TOTSLAB) / SPLITK;
    const int ks1 = ((ts + 1) * TOTSLAB) / SPLITK;
    const int iters = ks1 - ks0;

    const uint32_t sbase = s2u(smraw);

    const int arow = t >> 1;
    const int acb = (t & 1) * 4;
    const char* agp = (const char*)(g_ah + (size_t)arow * KTOT + ks0 * 64);
    uint32_t aoff[4];
#pragma unroll
    for (int c = 0; c < 4; c++)
        aoff[c] = sw128((uint32_t)arow * 128u + (uint32_t)(acb + c) * 16u);
    const int brow = t >> 2;
    const int bcb = (t & 3) * 2;
    const char* bgp = (const char*)(g_bh + (size_t)(n0 + brow) * KTOT + ks0 * 64);
    uint32_t boff[2];
#pragma unroll
    for (int c = 0; c < 2; c++)
        boff[c] = 32768u + sw128((uint32_t)brow * 128u + (uint32_t)(bcb + c) * 16u);

    const int rowa = wm * 64 + (lane & 15);
    const uint32_t xa = ((uint32_t)(rowa & 7)) << 4;
    uint32_t aob[4];
#pragma unroll
    for (int mi = 0; mi < 4; mi++)
        aob[mi] = (uint32_t)(rowa + mi * 16) * 128u + ((lane >> 4) << 4);
    const int rowb = wn * 32 + (lane & 15);
    const uint32_t xb = ((uint32_t)(rowb & 7)) << 4;
    uint32_t bob[2];
#pragma unroll
    for (int ng = 0; ng < 2; ng++)
        bob[ng] = 32768u + (uint32_t)(rowb + ng * 16) * 128u + ((lane >> 4) << 4);

    float acc[4][4][4];
#pragma unroll
    for (int i = 0; i < 4; i++)
#pragma unroll
        for (int j = 0; j < 4; j++)
#pragma unroll
            for (int e = 0; e < 4; e++) acc[i][j][e] = 0.f;

#pragma unroll
    for (int p = 0; p < 2; p++) {
        uint32_t sb = sbase + p * STG_BYTES;
        const char* ag = agp + (size_t)p * 128;
        const char* bg = bgp + (size_t)p * 128;
#pragma unroll
        for (int c = 0; c < 4; c++) cp16(sb + aoff[c], ag + (acb + c) * 16);
#pragma unroll
        for (int c = 0; c < 2; c++) cp16(sb + boff[c], bg + (bcb + c) * 16);
        asm volatile("cp.async.commit_group;");
    }

    int stg = 0;
    for (int it = 0; it < iters; it++) {
        asm volatile("cp.async.wait_group 1;");
        __syncthreads();

        const uint32_t sa = sbase + (uint32_t)stg * STG_BYTES;
#pragma unroll
        for (int kk = 0; kk < 4; kk++) {
            uint32_t af[4][4], bf[2][4];
#pragma unroll
            for (int mi = 0; mi < 4; mi++)
                ldm4(af[mi], sa + ((aob[mi] + kk * 32) ^ xa));
#pragma unroll
            for (int ng = 0; ng < 2; ng++)
                ldm4(bf[ng], sa + ((bob[ng] + kk * 32) ^ xb));
#pragma unroll
            for (int mi = 0; mi < 4; mi++) {
                mma16816(acc[mi][0], af[mi], bf[0][0], bf[0][2]);
                mma16816(acc[mi][1], af[mi], bf[0][1], bf[0][3]);
                mma16816(acc[mi][2], af[mi], bf[1][0], bf[1][2]);
                mma16816(acc[mi][3], af[mi], bf[1][1], bf[1][3]);
            }
        }

        const int nx = it + 2;
        if (nx < iters) {
            uint32_t sb = sbase + (uint32_t)((stg + 2) % 3) * STG_BYTES;
            const char* ag = agp + (size_t)nx * 128;
            const char* bg = bgp + (size_t)nx * 128;
#pragma unroll
            for (int c = 0; c < 4; c++) cp16(sb + aoff[c], ag + (acb + c) * 16);
#pragma unroll
            for (int c = 0; c < 2; c++) cp16(sb + boff[c], bg + (bcb + c) * 16);
        }
        asm volatile("cp.async.commit_group;");
        stg = (stg + 1) % 3;
    }

#pragma unroll
    for (int mi = 0; mi < 4; mi++) {
        const int m = wm * 64 + mi * 16 + (lane >> 2);
#pragma unroll
        for (int nj = 0; nj < 4; nj++) {
            const int n = n0 + wn * 32 + nj * 8 + (lane & 3) * 2;
            float* d = g_part + ((size_t)ts * 1024 + n) * 256 + m;
            d[0]       = acc[mi][nj][0];
            d[256]     = acc[mi][nj][1];
            d[8]       = acc[mi][nj][2];
            d[256 + 8] = acc[mi][nj][3];
        }
    }
}

// ---------------- reduce split-K + BN over batch + relu (fc1) ----------------
__global__ void k_bn1(const float* __restrict__ fb1,
                      const float* __restrict__ fg1,
                      const float* __restrict__ fbe1) {
    __shared__ float rs[256], rq[256];
    int o = blockIdx.x, b = threadIdx.x;
    float pre = fb1[o];
#pragma unroll
    for (int s = 0; s < NSPL; s++)
        pre += g_part[((size_t)s * 1024 + o) * 256 + b];
    rs[b] = pre; rq[b] = pre * pre;
    __syncthreads();
    for (int o2 = 128; o2 > 0; o2 >>= 1) {
        if (b < o2) { rs[b] += rs[b + o2]; rq[b] += rq[b + o2]; }
        __syncthreads();
    }
    float m = rs[0] * (1.f / 256.f);
    float v = rq[0] * (1.f / 256.f) - m * m;
    float sc = fg1[o] * rsqrtf(v + EPS_BN);
    float sh = fbe1[o] - m * sc;
    g_r1t[(size_t)o * 256 + b] = fmaxf(pre * sc + sh, 0.f);
}

// ---------------- fc2 GEMM + BN over batch + relu ----------------
__global__ void k_bn2(const float* __restrict__ fw2, const float* __restrict__ fb2,
                      const float* __restrict__ fg2, const float* __restrict__ fbe2) {
    __shared__ float w[1024];
    __shared__ float rs[256], rq[256];
    int j = blockIdx.x, b = threadIdx.x;
    for (int i = b; i < 1024; i += 256) w[i] = fw2[(size_t)j * 1024 + i];
    __syncthreads();
    float pre = fb2[j];
#pragma unroll 8
    for (int k = 0; k < 1024; k++)
        pre += g_r1t[((size_t)k << 8) + b] * w[k];
    rs[b] = pre; rq[b] = pre * pre;
    __syncthreads();
    for (int o2 = 128; o2 > 0; o2 >>= 1) {
        if (b < o2) { rs[b] += rs[b + o2]; rq[b] += rq[b + o2]; }
        __syncthreads();
    }
    float m = rs[0] * (1.f / 256.f);
    float v = rq[0] * (1.f / 256.f) - m * m;
    float sc = fg2[j] * rsqrtf(v + EPS_BN);
    float sh = fbe2[j] - m * sc;
    g_r2[(size_t)b * 256 + j] = fmaxf(pre * sc + sh, 0.f);
}

// ---------------- row-wise L2 normalize ----------------
__global__ void k_norm(float* __restrict__ out) {
    __shared__ float rs[256];
    int b = blockIdx.x, j = threadIdx.x;
    float v = g_r2[(size_t)b * 256 + j];
    rs[j] = v * v;
    __syncthreads();
    for (int o = 128; o > 0; o >>= 1) {
        if (j < o) rs[j] += rs[j + o];
        __syncthreads();
    }
    float nrm = fmaxf(sqrtf(rs[0]), 1e-12f);
    out[(size_t)b * 256 + j] = v / nrm;
}

// ---------------- launch (stats1 at ncu index 3) ----------------
extern "C" void kernel_launch(void* const* d_in, const int* in_sizes, int n_in,
                              void* d_out, int out_size) {
    const float* x    = (const float*)d_in[0];
    const float* w1   = (const float*)d_in[2];
    const float* b1   = (const float*)d_in[3];
    const float* g1   = (const float*)d_in[4];
    const float* be1  = (const float*)d_in[5];
    const float* w2   = (const float*)d_in[6];
    const float* b2   = (const float*)d_in[7];
    const float* g2   = (const float*)d_in[8];
    const float* be2  = (const float*)d_in[9];
    const float* w3   = (const float*)d_in[10];
    const float* b3   = (const float*)d_in[11];
    const float* g3   = (const float*)d_in[12];
    const float* be3  = (const float*)d_in[13];
    const float* fw1  = (const float*)d_in[14];
    const float* fb1  = (const float*)d_in[15];
    const float* fg1  = (const float*)d_in[16];
    const float* fbe1 = (const float*)d_in[17];
    const float* fw2  = (const float*)d_in[18];
    const float* fb2  = (const float*)d_in[19];
    const float* fg2  = (const float*)d_in[20];
    const float* fbe2 = (const float*)d_in[21];
    float* out = (float*)d_out;

    cudaFuncSetAttribute(k_gemm, cudaFuncAttributeMaxDynamicSharedMemorySize, GEMM_SMEM);

    const size_t n4 = (size_t)1024 * KTOT / 4;
    const size_t c1 = n4 / 3, c2 = 2 * n4 / 3;
    k_convB<<<1024, 256>>>(fw1, 0, c1);
    k_convB<<<1024, 256>>>(fw1, c1, c2);
    k_convB<<<1024, 256>>>(fw1, c2, n4);
    k_stats1<<<GS1, 256>>>(x, w1, b1);     // index 3 -> ncu capture target
    k_fin1<<<1, 256>>>(g1, be1);
    k_stats2<<<GS, 256>>>(w2, b2);
    k_fin2<<<1, 256>>>(g2, be2);
    k_stats3<<<GS, 256>>>(w3, b3);
    k_fin3<<<1, 256>>>(g3, be3);
    k_soft<<<NSEG, 256>>>();
    k_pool<<<1184, 256>>>(x);
    k_gemm<<<GEMM_CTAS, 512, GEMM_SMEM>>>();
    k_bn1<<<1024, 256>>>(fb1, fg1, fbe1);
    k_bn2<<<256, 256>>>(fw2, fb2, fg2, fbe2);
    k_norm<<<NSEG, 256>>>(out);
}